// round 1
// baseline (speedup 1.0000x reference)
#include <cuda_runtime.h>
#include <math.h>

// ---------------------------------------------------------------------------
// Problem constants: B=1, D=16, H=64, W=64, C=128, WS=8, SS=4, NH=4, hd=32
//   tokens = 65536, windows = 128, N(window) = 512
// ---------------------------------------------------------------------------
#define TOK   65536
#define CCH   128
#define NWIN  128
#define WN    512          // tokens per window
#define NH    4
#define HD    32
#define MLPH  512

// Scratch (static device globals; no allocations allowed)
__device__ float g_xw [TOK * CCH];     // LN1 + shift + window-partitioned
__device__ float g_qkv[TOK * 384];     // qkv, window-token order
__device__ float g_rpe[NH * WN * WN];  // precomputed rel pos bias tables
__device__ float g_ao [TOK * CCH];     // attention output (window-token order)
__device__ float g_y  [TOK * CCH];     // x + proj(attn)  (spatial order)
__device__ float g_h2 [TOK * CCH];     // LN2(y)
__device__ float g_mlp[TOK * MLPH];    // gelu(mlp1)

// ---------------------------------------------------------------------------
// LN1 + roll(-4,-4,-4) + window partition.
// Output row m = win*512 + nl; reads source spatial token t = shifted+4 (mod).
// One warp per token.
// ---------------------------------------------------------------------------
__global__ __launch_bounds__(256) void ln1_shift_kernel(
    const float* __restrict__ x, const float* __restrict__ g,
    const float* __restrict__ b, float* __restrict__ out)
{
    int m    = blockIdx.x * 8 + (threadIdx.x >> 5);
    int lane = threadIdx.x & 31;
    int win = m >> 9, nl = m & 511;
    int wd = win >> 6, wh = (win >> 3) & 7, ww = win & 7;
    int nd = nl >> 6,  nh = (nl >> 3) & 7,  nw = nl & 7;
    int d  = ((wd * 8 + nd) + 4) & 15;
    int hh = ((wh * 8 + nh) + 4) & 63;
    int w  = ((ww * 8 + nw) + 4) & 63;
    int t  = (d * 64 + hh) * 64 + w;

    float4 v = ((const float4*)(x + (size_t)t * CCH))[lane];
    float s  = v.x + v.y + v.z + v.w;
    float s2 = v.x * v.x + v.y * v.y + v.z * v.z + v.w * v.w;
    #pragma unroll
    for (int o = 16; o; o >>= 1) {
        s  += __shfl_xor_sync(0xffffffffu, s,  o);
        s2 += __shfl_xor_sync(0xffffffffu, s2, o);
    }
    float mean = s * (1.f / 128.f);
    float var  = s2 * (1.f / 128.f) - mean * mean;
    float inv  = rsqrtf(var + 1e-5f);
    float4 gg = ((const float4*)g)[lane];
    float4 bb = ((const float4*)b)[lane];
    float4 r;
    r.x = (v.x - mean) * inv * gg.x + bb.x;
    r.y = (v.y - mean) * inv * gg.y + bb.y;
    r.z = (v.z - mean) * inv * gg.z + bb.z;
    r.w = (v.w - mean) * inv * gg.w + bb.w;
    ((float4*)(out + (size_t)m * CCH))[lane] = r;
}

// Plain per-row LN (LN2)
__global__ __launch_bounds__(256) void ln2_kernel(
    const float* __restrict__ x, const float* __restrict__ g,
    const float* __restrict__ b, float* __restrict__ out)
{
    int m    = blockIdx.x * 8 + (threadIdx.x >> 5);
    int lane = threadIdx.x & 31;
    float4 v = ((const float4*)(x + (size_t)m * CCH))[lane];
    float s  = v.x + v.y + v.z + v.w;
    float s2 = v.x * v.x + v.y * v.y + v.z * v.z + v.w * v.w;
    #pragma unroll
    for (int o = 16; o; o >>= 1) {
        s  += __shfl_xor_sync(0xffffffffu, s,  o);
        s2 += __shfl_xor_sync(0xffffffffu, s2, o);
    }
    float mean = s * (1.f / 128.f);
    float var  = s2 * (1.f / 128.f) - mean * mean;
    float inv  = rsqrtf(var + 1e-5f);
    float4 gg = ((const float4*)g)[lane];
    float4 bb = ((const float4*)b)[lane];
    float4 r;
    r.x = (v.x - mean) * inv * gg.x + bb.x;
    r.y = (v.y - mean) * inv * gg.y + bb.y;
    r.z = (v.z - mean) * inv * gg.z + bb.z;
    r.w = (v.w - mean) * inv * gg.w + bb.w;
    ((float4*)(out + (size_t)m * CCH))[lane] = r;
}

// ---------------------------------------------------------------------------
// Precompute rpe[h][n][j] = rel_bias[rel_index[n*512+j]*4 + h]
// ---------------------------------------------------------------------------
__global__ void rpe_kernel(const int* __restrict__ ri, const float* __restrict__ rb,
                           float* __restrict__ rpe)
{
    int idx = blockIdx.x * 256 + threadIdx.x;   // 0 .. 262143
    int r = ri[idx];
    #pragma unroll
    for (int h = 0; h < NH; h++)
        rpe[h * (WN * WN) + idx] = rb[r * NH + h];
}

// ---------------------------------------------------------------------------
// Generic NT GEMM: C[M,N] = A[M,K] @ B[N,K]^T (+ epilogue)
// BM=BN=64, BK=16, 256 threads, 4x4 micro-tile. M,N,K all multiples of tiles.
// MODE 0: + bias
// MODE 1: gelu(+ bias)
// MODE 2: + bias + R[m*N+n]                       (final MLP residual)
// MODE 3: window-reverse + roll(+4) scatter: out[t*128+n] = R[t*128+n]+bias+c
// ---------------------------------------------------------------------------
template <int MODE>
__global__ __launch_bounds__(256) void gemm_nt(
    const float* __restrict__ A, const float* __restrict__ B,
    const float* __restrict__ bias, float* __restrict__ Cc,
    const float* __restrict__ R, int M, int N, int K)
{
    __shared__ float As[16][64];
    __shared__ float Bs[16][64];
    int tid = threadIdx.x;
    int bm = blockIdx.x * 64, bn = blockIdx.y * 64;
    int lr = tid >> 2, lk = (tid & 3) * 4;
    const float* Ag = A + (size_t)(bm + lr) * K + lk;
    const float* Bg = B + (size_t)(bn + lr) * K + lk;
    int tm = (tid >> 4) * 4, tn = (tid & 15) * 4;
    float acc[4][4] = {};

    for (int kt = 0; kt < K; kt += 16) {
        float4 av = *(const float4*)(Ag + kt);
        float4 bv = *(const float4*)(Bg + kt);
        __syncthreads();
        As[lk + 0][lr] = av.x; As[lk + 1][lr] = av.y;
        As[lk + 2][lr] = av.z; As[lk + 3][lr] = av.w;
        Bs[lk + 0][lr] = bv.x; Bs[lk + 1][lr] = bv.y;
        Bs[lk + 2][lr] = bv.z; Bs[lk + 3][lr] = bv.w;
        __syncthreads();
        #pragma unroll
        for (int k = 0; k < 16; k++) {
            float4 a4 = *(const float4*)&As[k][tm];
            float4 b4 = *(const float4*)&Bs[k][tn];
            acc[0][0] += a4.x * b4.x; acc[0][1] += a4.x * b4.y;
            acc[0][2] += a4.x * b4.z; acc[0][3] += a4.x * b4.w;
            acc[1][0] += a4.y * b4.x; acc[1][1] += a4.y * b4.y;
            acc[1][2] += a4.y * b4.z; acc[1][3] += a4.y * b4.w;
            acc[2][0] += a4.z * b4.x; acc[2][1] += a4.z * b4.y;
            acc[2][2] += a4.z * b4.z; acc[2][3] += a4.z * b4.w;
            acc[3][0] += a4.w * b4.x; acc[3][1] += a4.w * b4.y;
            acc[3][2] += a4.w * b4.z; acc[3][3] += a4.w * b4.w;
        }
    }

    #pragma unroll
    for (int i = 0; i < 4; i++) {
        int m = bm + tm + i;
        int t = m;
        if (MODE == 3) {
            int win = m >> 9, nl = m & 511;
            int wd = win >> 6, wh = (win >> 3) & 7, ww = win & 7;
            int nd = nl >> 6,  nh = (nl >> 3) & 7,  nw = nl & 7;
            int d  = ((wd * 8 + nd) + 4) & 15;
            int hh = ((wh * 8 + nh) + 4) & 63;
            int w  = ((ww * 8 + nw) + 4) & 63;
            t = (d * 64 + hh) * 64 + w;
        }
        #pragma unroll
        for (int j = 0; j < 4; j++) {
            int nn = bn + tn + j;
            float val = acc[i][j] + bias[nn];
            if (MODE == 0) {
                Cc[(size_t)m * N + nn] = val;
            } else if (MODE == 1) {
                Cc[(size_t)m * N + nn] = 0.5f * val * (1.0f + erff(val * 0.70710678118654752f));
            } else if (MODE == 2) {
                Cc[(size_t)m * N + nn] = val + R[(size_t)m * N + nn];
            } else { // MODE 3
                Cc[(size_t)t * CCH + nn] = val + R[(size_t)t * CCH + nn];
            }
        }
    }
}

// ---------------------------------------------------------------------------
// Attention: one block per (head, window). 512 threads, 1 query row each.
// K/V streamed through smem in 128-row chunks; online softmax; q/acc in regs.
// ---------------------------------------------------------------------------
__global__ __launch_bounds__(512) void attn_kernel(
    const float* __restrict__ qkv, const float* __restrict__ rpe,
    const float* __restrict__ mask, float* __restrict__ out)
{
    int head = blockIdx.x, win = blockIdx.y;
    int n = threadIdx.x;
    __shared__ float Ks[128][32];
    __shared__ float Vs[128][32];
    const float scale = 0.17677669529663687f;   // 1/sqrt(32)

    float q[32];
    {
        const float4* qp = (const float4*)(qkv + (size_t)(win * WN + n) * 384 + head * HD);
        #pragma unroll
        for (int i = 0; i < 8; i++) {
            float4 v = qp[i];
            q[4*i+0] = v.x * scale; q[4*i+1] = v.y * scale;
            q[4*i+2] = v.z * scale; q[4*i+3] = v.w * scale;
        }
    }
    float acc[32];
    #pragma unroll
    for (int i = 0; i < 32; i++) acc[i] = 0.f;
    float mx = -1e30f, l = 0.f;

    const float* rp = rpe  + (size_t)head * (WN * WN) + (size_t)n * WN;
    const float* mp = mask + (size_t)win  * (WN * WN) + (size_t)n * WN;

    for (int c0 = 0; c0 < WN; c0 += 128) {
        __syncthreads();
        for (int i = threadIdx.x; i < 128 * 8; i += 512) {
            int r = i >> 3, cq = (i & 7) * 4;
            const float* base = qkv + (size_t)(win * WN + c0 + r) * 384 + head * HD;
            *(float4*)&Ks[r][cq] = *(const float4*)(base + 128 + cq);
            *(float4*)&Vs[r][cq] = *(const float4*)(base + 256 + cq);
        }
        __syncthreads();
        for (int j = 0; j < 128; j++) {
            float s0 = 0.f, s1 = 0.f, s2 = 0.f, s3 = 0.f;
            #pragma unroll
            for (int c = 0; c < 8; c++) {
                s0 += q[4*c+0] * Ks[j][4*c+0];
                s1 += q[4*c+1] * Ks[j][4*c+1];
                s2 += q[4*c+2] * Ks[j][4*c+2];
                s3 += q[4*c+3] * Ks[j][4*c+3];
            }
            float s = (s0 + s1) + (s2 + s3) + rp[c0 + j] + mp[c0 + j];
            if (s > mx) {
                float corr = __expf(mx - s);
                l *= corr;
                #pragma unroll
                for (int c = 0; c < 32; c++) acc[c] *= corr;
                mx = s;
            }
            float p = __expf(s - mx);
            l += p;
            #pragma unroll
            for (int c = 0; c < 32; c++) acc[c] += p * Vs[j][c];
        }
    }

    float inv = 1.f / l;
    float4* op = (float4*)(out + (size_t)(win * WN + n) * CCH + head * HD);
    #pragma unroll
    for (int i = 0; i < 8; i++) {
        float4 v;
        v.x = acc[4*i+0] * inv; v.y = acc[4*i+1] * inv;
        v.z = acc[4*i+2] * inv; v.w = acc[4*i+3] * inv;
        op[i] = v;
    }
}

// ---------------------------------------------------------------------------
extern "C" void kernel_launch(void* const* d_in, const int* in_sizes, int n_in,
                              void* d_out, int out_size)
{
    const float* x         = (const float*)d_in[0];
    const float* attn_mask = (const float*)d_in[1];
    const int*   rel_index = (const int*)  d_in[2];
    const float* rel_bias  = (const float*)d_in[3];
    const float* qkv_w     = (const float*)d_in[4];
    const float* qkv_b     = (const float*)d_in[5];
    const float* proj_w    = (const float*)d_in[6];
    const float* proj_b    = (const float*)d_in[7];
    const float* n1g       = (const float*)d_in[8];
    const float* n1b       = (const float*)d_in[9];
    const float* n2g       = (const float*)d_in[10];
    const float* n2b       = (const float*)d_in[11];
    const float* w1        = (const float*)d_in[12];
    const float* b1        = (const float*)d_in[13];
    const float* w2        = (const float*)d_in[14];
    const float* b2        = (const float*)d_in[15];
    float* out = (float*)d_out;

    float *xw, *qkv, *rpe, *ao, *y, *h2, *mlp;
    cudaGetSymbolAddress((void**)&xw,  g_xw);
    cudaGetSymbolAddress((void**)&qkv, g_qkv);
    cudaGetSymbolAddress((void**)&rpe, g_rpe);
    cudaGetSymbolAddress((void**)&ao,  g_ao);
    cudaGetSymbolAddress((void**)&y,   g_y);
    cudaGetSymbolAddress((void**)&h2,  g_h2);
    cudaGetSymbolAddress((void**)&mlp, g_mlp);

    ln1_shift_kernel<<<TOK / 8, 256>>>(x, n1g, n1b, xw);
    gemm_nt<0><<<dim3(TOK / 64, 384 / 64), 256>>>(xw, qkv_w, qkv_b, qkv, nullptr,
                                                  TOK, 384, 128);
    rpe_kernel<<<(WN * WN) / 256, 256>>>(rel_index, rel_bias, rpe);
    attn_kernel<<<dim3(NH, NWIN), 512>>>(qkv, rpe, attn_mask, ao);
    gemm_nt<3><<<dim3(TOK / 64, 128 / 64), 256>>>(ao, proj_w, proj_b, y, x,
                                                  TOK, 128, 128);
    ln2_kernel<<<TOK / 8, 256>>>(y, n2g, n2b, h2);
    gemm_nt<1><<<dim3(TOK / 64, 512 / 64), 256>>>(h2, w1, b1, mlp, nullptr,
                                                  TOK, 512, 128);
    gemm_nt<2><<<dim3(TOK / 64, 128 / 64), 256>>>(mlp, w2, b2, out, y,
                                                  TOK, 128, 512);
}

// round 4
// speedup vs baseline: 1.2904x; 1.2904x over previous
#include <cuda_runtime.h>
#include <math.h>
#include <stdint.h>

// Problem constants: B=1, D=16, H=64, W=64, C=128, WS=8, SS=4, NH=4, hd=32
#define TOK   65536
#define CCH   128
#define NWIN  128
#define WN    512
#define NH    4
#define HD    32
#define MLPH  512

// Scratch
__device__ float g_xw [TOK * CCH];
__device__ float g_qkv[TOK * 384];
__device__ float g_rpe[NH * WN * WN];
__device__ float g_ao [TOK * CCH];
__device__ float g_y  [TOK * CCH];
__device__ float g_h2 [TOK * CCH];
__device__ float g_mlp[TOK * MLPH];

// ---------------------------------------------------------------------------
// Helpers: tf32 mma m16n8k8, hi/lo split (3xTF32), cp.async
// ---------------------------------------------------------------------------
__device__ __forceinline__ uint32_t f2tf(float f) {
    uint32_t r;
    asm("cvt.rna.tf32.f32 %0, %1;" : "=r"(r) : "f"(f));
    return r;
}
__device__ __forceinline__ void split_tf(float x, uint32_t& hi, uint32_t& lo) {
    hi = f2tf(x);
    lo = f2tf(x - __uint_as_float(hi));
}
__device__ __forceinline__ void mma8(float* c, const uint32_t* a, const uint32_t* b) {
    asm volatile(
        "mma.sync.aligned.m16n8k8.row.col.f32.tf32.tf32.f32 "
        "{%0,%1,%2,%3},{%4,%5,%6,%7},{%8,%9},{%0,%1,%2,%3};"
        : "+f"(c[0]), "+f"(c[1]), "+f"(c[2]), "+f"(c[3])
        : "r"(a[0]), "r"(a[1]), "r"(a[2]), "r"(a[3]), "r"(b[0]), "r"(b[1]));
}
// 3xTF32: c += ahi*bhi + ahi*blo + alo*bhi
__device__ __forceinline__ void mma3(float* c, const uint32_t* ah, const uint32_t* al,
                                     const uint32_t* bh, const uint32_t* bl) {
    mma8(c, ah, bl);
    mma8(c, al, bh);
    mma8(c, ah, bh);
}
__device__ __forceinline__ void cpa16(float* dst, const float* src) {
    unsigned d = (unsigned)__cvta_generic_to_shared(dst);
    asm volatile("cp.async.cg.shared.global [%0], [%1], 16;" :: "r"(d), "l"(src));
}
#define CP_COMMIT() asm volatile("cp.async.commit_group;")
#define CP_WAIT0()  asm volatile("cp.async.wait_group 0;")

// ---------------------------------------------------------------------------
// LN1 + roll(-4,-4,-4) + window partition (one warp per token)
// ---------------------------------------------------------------------------
__global__ __launch_bounds__(256) void ln1_shift_kernel(
    const float* __restrict__ x, const float* __restrict__ g,
    const float* __restrict__ b, float* __restrict__ out)
{
    int m    = blockIdx.x * 8 + (threadIdx.x >> 5);
    int lane = threadIdx.x & 31;
    int win = m >> 9, nl = m & 511;
    int wd = win >> 6, wh = (win >> 3) & 7, ww = win & 7;
    int nd = nl >> 6,  nh = (nl >> 3) & 7,  nw = nl & 7;
    int d  = ((wd * 8 + nd) + 4) & 15;
    int hh = ((wh * 8 + nh) + 4) & 63;
    int w  = ((ww * 8 + nw) + 4) & 63;
    int t  = (d * 64 + hh) * 64 + w;

    float4 v = ((const float4*)(x + (size_t)t * CCH))[lane];
    float s  = v.x + v.y + v.z + v.w;
    float s2 = v.x * v.x + v.y * v.y + v.z * v.z + v.w * v.w;
    #pragma unroll
    for (int o = 16; o; o >>= 1) {
        s  += __shfl_xor_sync(0xffffffffu, s,  o);
        s2 += __shfl_xor_sync(0xffffffffu, s2, o);
    }
    float mean = s * (1.f / 128.f);
    float var  = s2 * (1.f / 128.f) - mean * mean;
    float inv  = rsqrtf(var + 1e-5f);
    float4 gg = ((const float4*)g)[lane];
    float4 bb = ((const float4*)b)[lane];
    float4 r;
    r.x = (v.x - mean) * inv * gg.x + bb.x;
    r.y = (v.y - mean) * inv * gg.y + bb.y;
    r.z = (v.z - mean) * inv * gg.z + bb.z;
    r.w = (v.w - mean) * inv * gg.w + bb.w;
    ((float4*)(out + (size_t)m * CCH))[lane] = r;
}

__global__ __launch_bounds__(256) void ln2_kernel(
    const float* __restrict__ x, const float* __restrict__ g,
    const float* __restrict__ b, float* __restrict__ out)
{
    int m    = blockIdx.x * 8 + (threadIdx.x >> 5);
    int lane = threadIdx.x & 31;
    float4 v = ((const float4*)(x + (size_t)m * CCH))[lane];
    float s  = v.x + v.y + v.z + v.w;
    float s2 = v.x * v.x + v.y * v.y + v.z * v.z + v.w * v.w;
    #pragma unroll
    for (int o = 16; o; o >>= 1) {
        s  += __shfl_xor_sync(0xffffffffu, s,  o);
        s2 += __shfl_xor_sync(0xffffffffu, s2, o);
    }
    float mean = s * (1.f / 128.f);
    float var  = s2 * (1.f / 128.f) - mean * mean;
    float inv  = rsqrtf(var + 1e-5f);
    float4 gg = ((const float4*)g)[lane];
    float4 bb = ((const float4*)b)[lane];
    float4 r;
    r.x = (v.x - mean) * inv * gg.x + bb.x;
    r.y = (v.y - mean) * inv * gg.y + bb.y;
    r.z = (v.z - mean) * inv * gg.z + bb.z;
    r.w = (v.w - mean) * inv * gg.w + bb.w;
    ((float4*)(out + (size_t)m * CCH))[lane] = r;
}

// ---------------------------------------------------------------------------
// rpe[h][n][j] = rel_bias[rel_index[n*512+j]*4 + h]
// ---------------------------------------------------------------------------
__global__ void rpe_kernel(const int* __restrict__ ri, const float* __restrict__ rb,
                           float* __restrict__ rpe)
{
    int idx = blockIdx.x * 256 + threadIdx.x;
    int r = ri[idx];
    #pragma unroll
    for (int h = 0; h < NH; h++)
        rpe[h * (WN * WN) + idx] = rb[r * NH + h];
}

// ---------------------------------------------------------------------------
// 3xTF32 GEMM: C[M,N] = A[M,K] @ B[N,K]^T + epilogue
// Block 128x128, BK=32, 8 warps (2m x 4n), warp tile 64x32.
// MODE 0: +bias     MODE 1: gelu(+bias)   MODE 2: +bias+R[m,n]
// MODE 3: +bias+R[t,n] scattered to C[t,n] with window-reverse + roll(+4)
// ---------------------------------------------------------------------------
template <int MODE>
__global__ __launch_bounds__(256) void gemm_tf32(
    const float* __restrict__ A, const float* __restrict__ B,
    const float* __restrict__ bias, float* __restrict__ C,
    const float* __restrict__ R, int M, int N, int K)
{
    __shared__ float As[128][36];
    __shared__ float Bs[128][36];
    int tid = threadIdx.x, lane = tid & 31, warp = tid >> 5;
    int bm = blockIdx.x * 128, bn = blockIdx.y * 128;
    int wm = (warp >> 2) * 64, wn = (warp & 3) * 32;
    int r4 = lane >> 2, c4 = lane & 3;

    float acc[4][4][4];
    #pragma unroll
    for (int i = 0; i < 4; i++)
        #pragma unroll
        for (int j = 0; j < 4; j++)
            #pragma unroll
            for (int c = 0; c < 4; c++) acc[i][j][c] = 0.f;

    int lr = tid >> 1, lc = (tid & 1) * 16;
    const float* Ag = A + (size_t)(bm + lr) * K + lc;
    const float* Bg = B + (size_t)(bn + lr) * K + lc;

    for (int kt = 0; kt < K; kt += 32) {
        __syncthreads();
        #pragma unroll
        for (int s = 0; s < 4; s++) {
            cpa16(&As[lr][lc + s * 4], Ag + kt + s * 4);
            cpa16(&Bs[lr][lc + s * 4], Bg + kt + s * 4);
        }
        CP_COMMIT();
        CP_WAIT0();
        __syncthreads();
        #pragma unroll
        for (int k8 = 0; k8 < 32; k8 += 8) {
            uint32_t ah[4][4], al[4][4], bh[4][2], bl[4][2];
            #pragma unroll
            for (int i = 0; i < 4; i++) {
                int r = wm + 16 * i;
                split_tf(As[r +     r4][k8 +     c4], ah[i][0], al[i][0]);
                split_tf(As[r + 8 + r4][k8 +     c4], ah[i][1], al[i][1]);
                split_tf(As[r +     r4][k8 + 4 + c4], ah[i][2], al[i][2]);
                split_tf(As[r + 8 + r4][k8 + 4 + c4], ah[i][3], al[i][3]);
            }
            #pragma unroll
            for (int j = 0; j < 4; j++) {
                int c = wn + 8 * j;
                split_tf(Bs[c + r4][k8 +     c4], bh[j][0], bl[j][0]);
                split_tf(Bs[c + r4][k8 + 4 + c4], bh[j][1], bl[j][1]);
            }
            #pragma unroll
            for (int i = 0; i < 4; i++)
                #pragma unroll
                for (int j = 0; j < 4; j++)
                    mma3(acc[i][j], ah[i], al[i], bh[j], bl[j]);
        }
    }

    #pragma unroll
    for (int i = 0; i < 4; i++) {
        int r0 = bm + wm + 16 * i + r4;
        #pragma unroll
        for (int h = 0; h < 2; h++) {
            int m = r0 + 8 * h;
            size_t trow = m;
            if (MODE == 3) {
                int win = m >> 9, nl = m & 511;
                int wd = win >> 6, wh = (win >> 3) & 7, ww = win & 7;
                int nd = nl >> 6,  nh = (nl >> 3) & 7,  nw = nl & 7;
                int d  = ((wd * 8 + nd) + 4) & 15;
                int hh = ((wh * 8 + nh) + 4) & 63;
                int w  = ((ww * 8 + nw) + 4) & 63;
                trow = (size_t)((d * 64 + hh) * 64 + w);
            }
            #pragma unroll
            for (int j = 0; j < 4; j++) {
                int c0 = bn + wn + 8 * j + 2 * c4;
                float v0 = acc[i][j][2 * h + 0] + bias[c0];
                float v1 = acc[i][j][2 * h + 1] + bias[c0 + 1];
                if (MODE == 0) {
                    *(float2*)(C + (size_t)m * N + c0) = make_float2(v0, v1);
                } else if (MODE == 1) {
                    float g0 = 0.5f * v0 * (1.0f + erff(v0 * 0.70710678118654752f));
                    float g1 = 0.5f * v1 * (1.0f + erff(v1 * 0.70710678118654752f));
                    *(float2*)(C + (size_t)m * N + c0) = make_float2(g0, g1);
                } else if (MODE == 2) {
                    float2 rr = *(const float2*)(R + (size_t)m * N + c0);
                    *(float2*)(C + (size_t)m * N + c0) = make_float2(v0 + rr.x, v1 + rr.y);
                } else {
                    float2 rr = *(const float2*)(R + trow * CCH + c0);
                    *(float2*)(C + trow * CCH + c0) = make_float2(v0 + rr.x, v1 + rr.y);
                }
            }
        }
    }
}

// ---------------------------------------------------------------------------
// Tensor-core attention (3xTF32). Block = (head, win, q-tile 128), 8 warps.
// P fragment produced from S via intra-warp shuffle transpose (no smem P).
// Scores bounded, so plain exp (no running max). Mask from Swin geometry.
// ---------------------------------------------------------------------------
__global__ __launch_bounds__(256) void attn_mma(
    const float* __restrict__ qkv, const float* __restrict__ rpe,
    float* __restrict__ out)
{
    __shared__ float Ks[64][36];
    __shared__ float Vs[64][40];
    __shared__ unsigned char regtab[512];

    int head = blockIdx.x, win = blockIdx.y, qt = blockIdx.z;
    int tid = threadIdx.x, lane = tid & 31, warp = tid >> 5;
    int r4 = lane >> 2, c4 = lane & 3;

    {
        int wd = win >> 6, wh = (win >> 3) & 7, ww = win & 7;
        for (int n = tid; n < 512; n += 256) {
            int nd = n >> 6, nh = (n >> 3) & 7, nw = n & 7;
            int rd = (wd == 1) ? ((nd < 4) ? 1 : 2) : 0;
            int rh = (wh == 7) ? ((nh < 4) ? 1 : 2) : 0;
            int rw = (ww == 7) ? ((nw < 4) ? 1 : 2) : 0;
            regtab[n] = (unsigned char)(rd * 9 + rh * 3 + rw);
        }
    }

    int qr = qt * 128 + warp * 16;
    const float scale = 0.17677669529663687f;
    const float* qb = qkv + (size_t)(win * WN + qr) * 384 + head * HD;
    uint32_t qh[4][4], ql[4][4];
    #pragma unroll
    for (int k8 = 0; k8 < 4; k8++) {
        split_tf(scale * qb[(size_t)r4       * 384 + k8 * 8 +     c4], qh[k8][0], ql[k8][0]);
        split_tf(scale * qb[(size_t)(r4 + 8) * 384 + k8 * 8 +     c4], qh[k8][1], ql[k8][1]);
        split_tf(scale * qb[(size_t)r4       * 384 + k8 * 8 + 4 + c4], qh[k8][2], ql[k8][2]);
        split_tf(scale * qb[(size_t)(r4 + 8) * 384 + k8 * 8 + 4 + c4], qh[k8][3], ql[k8][3]);
    }

    float o[4][4];
    #pragma unroll
    for (int j = 0; j < 4; j++)
        #pragma unroll
        for (int c = 0; c < 4; c++) o[j][c] = 0.f;
    float l0 = 0.f, l1 = 0.f;

    __syncthreads();
    int row0 = qr + r4, row1 = row0 + 8;
    int rr0 = regtab[row0], rr1 = regtab[row1];
    const float* rpb = rpe + ((size_t)head << 18);

    int ldrow = tid >> 2, ldsg = (tid & 3) * 8;
    // shuffle-transpose source lanes: column c of an 8-col block is held by
    // lane (r4*4 + (c>>1)), element (c&1). We need cols c4 and c4+4.
    int src0 = (lane & ~3) | (c4 >> 1);
    int src1 = src0 + 2;
    bool oddc = (c4 & 1);

    for (int c0 = 0; c0 < WN; c0 += 64) {
        const float* kb = qkv + (size_t)(win * WN + c0 + ldrow) * 384 + 128 + head * HD + ldsg;
        cpa16(&Ks[ldrow][ldsg],     kb);
        cpa16(&Ks[ldrow][ldsg + 4], kb + 4);
        cpa16(&Vs[ldrow][ldsg],     kb + 128);
        cpa16(&Vs[ldrow][ldsg + 4], kb + 132);
        CP_COMMIT();
        CP_WAIT0();
        __syncthreads();

        // S = Q K^T  (16 x 64 per warp), 3xTF32
        float s[8][4];
        #pragma unroll
        for (int nj = 0; nj < 8; nj++) {
            s[nj][0] = s[nj][1] = s[nj][2] = s[nj][3] = 0.f;
            #pragma unroll
            for (int k8 = 0; k8 < 4; k8++) {
                uint32_t kh[2], kl[2];
                split_tf(Ks[nj * 8 + r4][k8 * 8 +     c4], kh[0], kl[0]);
                split_tf(Ks[nj * 8 + r4][k8 * 8 + 4 + c4], kh[1], kl[1]);
                mma3(s[nj], qh[k8], ql[k8], kh, kl);
            }
        }

        // Per key-block: rpe + mask + exp -> P fragment via shuffle -> O += P V
        const float* rp0 = rpb + (size_t)row0 * WN + c0 + 2 * c4;
        const float* rp1 = rpb + (size_t)row1 * WN + c0 + 2 * c4;
        #pragma unroll
        for (int nj = 0; nj < 8; nj++) {
            int cc = c0 + nj * 8 + 2 * c4;
            float2 ra  = *(const float2*)(rp0 + nj * 8);
            float2 rb2 = *(const float2*)(rp1 + nj * 8);
            int rc0 = regtab[cc], rc1 = regtab[cc + 1];
            float e00 = (rr0 == rc0) ? __expf(s[nj][0] + ra.x)  : 0.f;
            float e01 = (rr0 == rc1) ? __expf(s[nj][1] + ra.y)  : 0.f;
            float e10 = (rr1 == rc0) ? __expf(s[nj][2] + rb2.x) : 0.f;
            float e11 = (rr1 == rc1) ? __expf(s[nj][3] + rb2.y) : 0.f;
            l0 += e00 + e01;
            l1 += e10 + e11;

            // transpose to A-fragment: p0=P[r4][c4], p1=P[r4+8][c4],
            //                          p2=P[r4][c4+4], p3=P[r4+8][c4+4]
            float a0 = __shfl_sync(0xffffffffu, e00, src0);
            float b0 = __shfl_sync(0xffffffffu, e01, src0);
            float a1 = __shfl_sync(0xffffffffu, e10, src0);
            float b1 = __shfl_sync(0xffffffffu, e11, src0);
            float a2 = __shfl_sync(0xffffffffu, e00, src1);
            float b2 = __shfl_sync(0xffffffffu, e01, src1);
            float a3 = __shfl_sync(0xffffffffu, e10, src1);
            float b3 = __shfl_sync(0xffffffffu, e11, src1);
            float p0 = oddc ? b0 : a0;
            float p1 = oddc ? b1 : a1;
            float p2 = oddc ? b2 : a2;
            float p3 = oddc ? b3 : a3;

            uint32_t ph[4], pl[4];
            split_tf(p0, ph[0], pl[0]);
            split_tf(p1, ph[1], pl[1]);
            split_tf(p2, ph[2], pl[2]);
            split_tf(p3, ph[3], pl[3]);

            #pragma unroll
            for (int dj = 0; dj < 4; dj++) {
                uint32_t vh[2], vl[2];
                split_tf(Vs[nj * 8 +     c4][dj * 8 + r4], vh[0], vl[0]);
                split_tf(Vs[nj * 8 + 4 + c4][dj * 8 + r4], vh[1], vl[1]);
                mma3(o[dj], ph, pl, vh, vl);
            }
        }
        __syncthreads();
    }

    l0 += __shfl_xor_sync(0xffffffffu, l0, 1);
    l0 += __shfl_xor_sync(0xffffffffu, l0, 2);
    l1 += __shfl_xor_sync(0xffffffffu, l1, 1);
    l1 += __shfl_xor_sync(0xffffffffu, l1, 2);
    float i0 = 1.f / l0, i1 = 1.f / l1;

    float* ob = out + (size_t)(win * WN + qr) * CCH + head * HD;
    #pragma unroll
    for (int nj = 0; nj < 4; nj++) {
        *(float2*)(ob + (size_t)r4       * CCH + nj * 8 + 2 * c4) =
            make_float2(o[nj][0] * i0, o[nj][1] * i0);
        *(float2*)(ob + (size_t)(r4 + 8) * CCH + nj * 8 + 2 * c4) =
            make_float2(o[nj][2] * i1, o[nj][3] * i1);
    }
}

// ---------------------------------------------------------------------------
extern "C" void kernel_launch(void* const* d_in, const int* in_sizes, int n_in,
                              void* d_out, int out_size)
{
    const float* x         = (const float*)d_in[0];
    const int*   rel_index = (const int*)  d_in[2];
    const float* rel_bias  = (const float*)d_in[3];
    const float* qkv_w     = (const float*)d_in[4];
    const float* qkv_b     = (const float*)d_in[5];
    const float* proj_w    = (const float*)d_in[6];
    const float* proj_b    = (const float*)d_in[7];
    const float* n1g       = (const float*)d_in[8];
    const float* n1b       = (const float*)d_in[9];
    const float* n2g       = (const float*)d_in[10];
    const float* n2b       = (const float*)d_in[11];
    const float* w1        = (const float*)d_in[12];
    const float* b1        = (const float*)d_in[13];
    const float* w2        = (const float*)d_in[14];
    const float* b2        = (const float*)d_in[15];
    float* out = (float*)d_out;

    float *xw, *qkv, *rpe, *ao, *y, *h2, *mlp;
    cudaGetSymbolAddress((void**)&xw,  g_xw);
    cudaGetSymbolAddress((void**)&qkv, g_qkv);
    cudaGetSymbolAddress((void**)&rpe, g_rpe);
    cudaGetSymbolAddress((void**)&ao,  g_ao);
    cudaGetSymbolAddress((void**)&y,   g_y);
    cudaGetSymbolAddress((void**)&h2,  g_h2);
    cudaGetSymbolAddress((void**)&mlp, g_mlp);

    ln1_shift_kernel<<<TOK / 8, 256>>>(x, n1g, n1b, xw);
    rpe_kernel<<<(WN * WN) / 256, 256>>>(rel_index, rel_bias, rpe);
    gemm_tf32<0><<<dim3(TOK / 128, 3), 256>>>(xw, qkv_w, qkv_b, qkv, nullptr,
                                              TOK, 384, 128);
    attn_mma<<<dim3(NH, NWIN, 4), 256>>>(qkv, rpe, ao);
    gemm_tf32<3><<<dim3(TOK / 128, 1), 256>>>(ao, proj_w, proj_b, y, x,
                                              TOK, 128, 128);
    ln2_kernel<<<TOK / 8, 256>>>(y, n2g, n2b, h2);
    gemm_tf32<1><<<dim3(TOK / 128, 4), 256>>>(h2, w1, b1, mlp, nullptr,
                                              TOK, 512, 128);
    gemm_tf32<2><<<dim3(TOK / 128, 1), 256>>>(mlp, w2, b2, out, y,
                                              TOK, 128, 512);
}

// round 5
// speedup vs baseline: 3.7040x; 2.8704x over previous
#include <cuda_runtime.h>
#include <math.h>
#include <stdint.h>

// Problem constants: B=1, D=16, H=64, W=64, C=128, WS=8, SS=4, NH=4, hd=32
#define TOK   65536
#define CCH   128
#define NWIN  128
#define WN    512
#define NH    4
#define HD    32
#define MLPH  512

// Scratch
__device__ float g_xw [TOK * CCH];
__device__ float g_qkv[TOK * 384];
__device__ float g_rpe[NH * WN * WN];
__device__ float g_ao [TOK * CCH];
__device__ float g_y  [TOK * CCH];
__device__ float g_h2 [TOK * CCH];
__device__ float g_mlp[TOK * MLPH];

// ---------------------------------------------------------------------------
// Helpers
// ---------------------------------------------------------------------------
__device__ __forceinline__ uint32_t f2tf(float f) {
    uint32_t r;
    asm("cvt.rna.tf32.f32 %0, %1;" : "=r"(r) : "f"(f));
    return r;
}
__device__ __forceinline__ void mma8(float* c, const uint32_t* a, const uint32_t* b) {
    asm volatile(
        "mma.sync.aligned.m16n8k8.row.col.f32.tf32.tf32.f32 "
        "{%0,%1,%2,%3},{%4,%5,%6,%7},{%8,%9},{%0,%1,%2,%3};"
        : "+f"(c[0]), "+f"(c[1]), "+f"(c[2]), "+f"(c[3])
        : "r"(a[0]), "r"(a[1]), "r"(a[2]), "r"(a[3]), "r"(b[0]), "r"(b[1]));
}
__device__ __forceinline__ void cpa16(float* dst, const float* src) {
    unsigned d = (unsigned)__cvta_generic_to_shared(dst);
    asm volatile("cp.async.cg.shared.global [%0], [%1], 16;" :: "r"(d), "l"(src));
}
#define CP_COMMIT() asm volatile("cp.async.commit_group;")
#define CP_WAIT(n)  asm volatile("cp.async.wait_group %0;" :: "n"(n))

// ---------------------------------------------------------------------------
// LN1 + roll(-4,-4,-4) + window partition (one warp per token)
// ---------------------------------------------------------------------------
__global__ __launch_bounds__(256) void ln1_shift_kernel(
    const float* __restrict__ x, const float* __restrict__ g,
    const float* __restrict__ b, float* __restrict__ out)
{
    int m    = blockIdx.x * 8 + (threadIdx.x >> 5);
    int lane = threadIdx.x & 31;
    int win = m >> 9, nl = m & 511;
    int wd = win >> 6, wh = (win >> 3) & 7, ww = win & 7;
    int nd = nl >> 6,  nh = (nl >> 3) & 7,  nw = nl & 7;
    int d  = ((wd * 8 + nd) + 4) & 15;
    int hh = ((wh * 8 + nh) + 4) & 63;
    int w  = ((ww * 8 + nw) + 4) & 63;
    int t  = (d * 64 + hh) * 64 + w;

    float4 v = ((const float4*)(x + (size_t)t * CCH))[lane];
    float s  = v.x + v.y + v.z + v.w;
    float s2 = v.x * v.x + v.y * v.y + v.z * v.z + v.w * v.w;
    #pragma unroll
    for (int o = 16; o; o >>= 1) {
        s  += __shfl_xor_sync(0xffffffffu, s,  o);
        s2 += __shfl_xor_sync(0xffffffffu, s2, o);
    }
    float mean = s * (1.f / 128.f);
    float var  = s2 * (1.f / 128.f) - mean * mean;
    float inv  = rsqrtf(var + 1e-5f);
    float4 gg = ((const float4*)g)[lane];
    float4 bb = ((const float4*)b)[lane];
    float4 r;
    r.x = (v.x - mean) * inv * gg.x + bb.x;
    r.y = (v.y - mean) * inv * gg.y + bb.y;
    r.z = (v.z - mean) * inv * gg.z + bb.z;
    r.w = (v.w - mean) * inv * gg.w + bb.w;
    ((float4*)(out + (size_t)m * CCH))[lane] = r;
}

__global__ __launch_bounds__(256) void ln2_kernel(
    const float* __restrict__ x, const float* __restrict__ g,
    const float* __restrict__ b, float* __restrict__ out)
{
    int m    = blockIdx.x * 8 + (threadIdx.x >> 5);
    int lane = threadIdx.x & 31;
    float4 v = ((const float4*)(x + (size_t)m * CCH))[lane];
    float s  = v.x + v.y + v.z + v.w;
    float s2 = v.x * v.x + v.y * v.y + v.z * v.z + v.w * v.w;
    #pragma unroll
    for (int o = 16; o; o >>= 1) {
        s  += __shfl_xor_sync(0xffffffffu, s,  o);
        s2 += __shfl_xor_sync(0xffffffffu, s2, o);
    }
    float mean = s * (1.f / 128.f);
    float var  = s2 * (1.f / 128.f) - mean * mean;
    float inv  = rsqrtf(var + 1e-5f);
    float4 gg = ((const float4*)g)[lane];
    float4 bb = ((const float4*)b)[lane];
    float4 r;
    r.x = (v.x - mean) * inv * gg.x + bb.x;
    r.y = (v.y - mean) * inv * gg.y + bb.y;
    r.z = (v.z - mean) * inv * gg.z + bb.z;
    r.w = (v.w - mean) * inv * gg.w + bb.w;
    ((float4*)(out + (size_t)m * CCH))[lane] = r;
}

// ---------------------------------------------------------------------------
// rpe[h][n][j] = rel_bias[rel_index[n*512+j]*4 + h]
// ---------------------------------------------------------------------------
__global__ void rpe_kernel(const int* __restrict__ ri, const float* __restrict__ rb,
                           float* __restrict__ rpe)
{
    int idx = blockIdx.x * 256 + threadIdx.x;
    int r = ri[idx];
    #pragma unroll
    for (int h = 0; h < NH; h++)
        rpe[h * (WN * WN) + idx] = rb[r * NH + h];
}

// ---------------------------------------------------------------------------
// tf32 GEMM: C[M,N] = A[M,K] @ B[N,K]^T + epilogue
// Block 128x128, BK=32, 8 warps (2m x 4n), warp tile 64x32.
// MODE 0: +bias     MODE 1: gelu(+bias)   MODE 2: +bias+R[m,n]
// MODE 3: +bias+R[t,n] scattered to C[t,n] with window-reverse + roll(+4)
// ---------------------------------------------------------------------------
template <int MODE>
__global__ __launch_bounds__(256) void gemm_tf32(
    const float* __restrict__ A, const float* __restrict__ B,
    const float* __restrict__ bias, float* __restrict__ C,
    const float* __restrict__ R, int M, int N, int K)
{
    __shared__ float As[128][36];
    __shared__ float Bs[128][36];
    int tid = threadIdx.x, lane = tid & 31, warp = tid >> 5;
    int bm = blockIdx.x * 128, bn = blockIdx.y * 128;
    int wm = (warp >> 2) * 64, wn = (warp & 3) * 32;
    int r4 = lane >> 2, c4 = lane & 3;

    float acc[4][4][4];
    #pragma unroll
    for (int i = 0; i < 4; i++)
        #pragma unroll
        for (int j = 0; j < 4; j++)
            #pragma unroll
            for (int c = 0; c < 4; c++) acc[i][j][c] = 0.f;

    int lr = tid >> 1, lc = (tid & 1) * 16;
    const float* Ag = A + (size_t)(bm + lr) * K + lc;
    const float* Bg = B + (size_t)(bn + lr) * K + lc;

    for (int kt = 0; kt < K; kt += 32) {
        __syncthreads();
        #pragma unroll
        for (int s = 0; s < 4; s++) {
            cpa16(&As[lr][lc + s * 4], Ag + kt + s * 4);
            cpa16(&Bs[lr][lc + s * 4], Bg + kt + s * 4);
        }
        CP_COMMIT();
        CP_WAIT(0);
        __syncthreads();
        #pragma unroll
        for (int k8 = 0; k8 < 32; k8 += 8) {
            uint32_t af[4][4], bf[4][2];
            #pragma unroll
            for (int i = 0; i < 4; i++) {
                int r = wm + 16 * i;
                af[i][0] = f2tf(As[r +     r4][k8 +     c4]);
                af[i][1] = f2tf(As[r + 8 + r4][k8 +     c4]);
                af[i][2] = f2tf(As[r +     r4][k8 + 4 + c4]);
                af[i][3] = f2tf(As[r + 8 + r4][k8 + 4 + c4]);
            }
            #pragma unroll
            for (int j = 0; j < 4; j++) {
                int c = wn + 8 * j;
                bf[j][0] = f2tf(Bs[c + r4][k8 +     c4]);
                bf[j][1] = f2tf(Bs[c + r4][k8 + 4 + c4]);
            }
            #pragma unroll
            for (int i = 0; i < 4; i++)
                #pragma unroll
                for (int j = 0; j < 4; j++)
                    mma8(acc[i][j], af[i], bf[j]);
        }
    }

    #pragma unroll
    for (int i = 0; i < 4; i++) {
        int r0 = bm + wm + 16 * i + r4;
        #pragma unroll
        for (int h = 0; h < 2; h++) {
            int m = r0 + 8 * h;
            size_t trow = m;
            if (MODE == 3) {
                int win = m >> 9, nl = m & 511;
                int wd = win >> 6, wh = (win >> 3) & 7, ww = win & 7;
                int nd = nl >> 6,  nh = (nl >> 3) & 7,  nw = nl & 7;
                int d  = ((wd * 8 + nd) + 4) & 15;
                int hh = ((wh * 8 + nh) + 4) & 63;
                int w  = ((ww * 8 + nw) + 4) & 63;
                trow = (size_t)((d * 64 + hh) * 64 + w);
            }
            #pragma unroll
            for (int j = 0; j < 4; j++) {
                int c0 = bn + wn + 8 * j + 2 * c4;
                float v0 = acc[i][j][2 * h + 0] + bias[c0];
                float v1 = acc[i][j][2 * h + 1] + bias[c0 + 1];
                if (MODE == 0) {
                    *(float2*)(C + (size_t)m * N + c0) = make_float2(v0, v1);
                } else if (MODE == 1) {
                    float g0 = 0.5f * v0 * (1.0f + erff(v0 * 0.70710678118654752f));
                    float g1 = 0.5f * v1 * (1.0f + erff(v1 * 0.70710678118654752f));
                    *(float2*)(C + (size_t)m * N + c0) = make_float2(g0, g1);
                } else if (MODE == 2) {
                    float2 rr = *(const float2*)(R + (size_t)m * N + c0);
                    *(float2*)(C + (size_t)m * N + c0) = make_float2(v0 + rr.x, v1 + rr.y);
                } else {
                    float2 rr = *(const float2*)(R + trow * CCH + c0);
                    *(float2*)(C + trow * CCH + c0) = make_float2(v0 + rr.x, v1 + rr.y);
                }
            }
        }
    }
}

// ---------------------------------------------------------------------------
// Tensor-core attention (tf32). Block = (head, win, q-tile 128), 8 warps.
// Double-buffered K/V via cp.async. P fragment via shuffle transpose.
// Scores bounded, plain exp. Mask from Swin shift geometry.
// ---------------------------------------------------------------------------
__global__ __launch_bounds__(256) void attn_mma(
    const float* __restrict__ qkv, const float* __restrict__ rpe,
    float* __restrict__ out)
{
    __shared__ float Ks[2][64][36];
    __shared__ float Vs[2][64][40];
    __shared__ unsigned char regtab[512];

    int head = blockIdx.x, win = blockIdx.y, qt = blockIdx.z;
    int tid = threadIdx.x, lane = tid & 31, warp = tid >> 5;
    int r4 = lane >> 2, c4 = lane & 3;

    {
        int wd = win >> 6, wh = (win >> 3) & 7, ww = win & 7;
        for (int n = tid; n < 512; n += 256) {
            int nd = n >> 6, nh = (n >> 3) & 7, nw = n & 7;
            int rd = (wd == 1) ? ((nd < 4) ? 1 : 2) : 0;
            int rh = (wh == 7) ? ((nh < 4) ? 1 : 2) : 0;
            int rw = (ww == 7) ? ((nw < 4) ? 1 : 2) : 0;
            regtab[n] = (unsigned char)(rd * 9 + rh * 3 + rw);
        }
    }

    int qr = qt * 128 + warp * 16;
    const float scale = 0.17677669529663687f;
    const float* qb = qkv + (size_t)(win * WN + qr) * 384 + head * HD;
    uint32_t qf[4][4];
    #pragma unroll
    for (int k8 = 0; k8 < 4; k8++) {
        qf[k8][0] = f2tf(scale * qb[(size_t)r4       * 384 + k8 * 8 +     c4]);
        qf[k8][1] = f2tf(scale * qb[(size_t)(r4 + 8) * 384 + k8 * 8 +     c4]);
        qf[k8][2] = f2tf(scale * qb[(size_t)r4       * 384 + k8 * 8 + 4 + c4]);
        qf[k8][3] = f2tf(scale * qb[(size_t)(r4 + 8) * 384 + k8 * 8 + 4 + c4]);
    }

    float o[4][4];
    #pragma unroll
    for (int j = 0; j < 4; j++)
        #pragma unroll
        for (int c = 0; c < 4; c++) o[j][c] = 0.f;
    float l0 = 0.f, l1 = 0.f;

    __syncthreads();
    int row0 = qr + r4, row1 = row0 + 8;
    int rr0 = regtab[row0], rr1 = regtab[row1];
    const float* rpb = rpe + ((size_t)head << 18);

    int ldrow = tid >> 2, ldsg = (tid & 3) * 8;
    int src0 = (lane & ~3) | (c4 >> 1);
    int src1 = src0 + 2;
    bool oddc = (c4 & 1);

    // prologue: load chunk 0 into buffer 0
    {
        const float* kb = qkv + (size_t)(win * WN + ldrow) * 384 + 128 + head * HD + ldsg;
        cpa16(&Ks[0][ldrow][ldsg],     kb);
        cpa16(&Ks[0][ldrow][ldsg + 4], kb + 4);
        cpa16(&Vs[0][ldrow][ldsg],     kb + 128);
        cpa16(&Vs[0][ldrow][ldsg + 4], kb + 132);
        CP_COMMIT();
    }

    #pragma unroll 1
    for (int ci = 0; ci < 8; ci++) {
        int cur = ci & 1;
        if (ci + 1 < 8) {
            int nxt = cur ^ 1;
            const float* kb = qkv + (size_t)(win * WN + (ci + 1) * 64 + ldrow) * 384
                              + 128 + head * HD + ldsg;
            cpa16(&Ks[nxt][ldrow][ldsg],     kb);
            cpa16(&Ks[nxt][ldrow][ldsg + 4], kb + 4);
            cpa16(&Vs[nxt][ldrow][ldsg],     kb + 128);
            cpa16(&Vs[nxt][ldrow][ldsg + 4], kb + 132);
            CP_COMMIT();
            CP_WAIT(1);
        } else {
            CP_WAIT(0);
        }
        __syncthreads();
        int c0 = ci * 64;

        // S = Q K^T  (16 x 64 per warp)
        float s[8][4];
        #pragma unroll
        for (int nj = 0; nj < 8; nj++) {
            s[nj][0] = s[nj][1] = s[nj][2] = s[nj][3] = 0.f;
            #pragma unroll
            for (int k8 = 0; k8 < 4; k8++) {
                uint32_t kf[2];
                kf[0] = f2tf(Ks[cur][nj * 8 + r4][k8 * 8 +     c4]);
                kf[1] = f2tf(Ks[cur][nj * 8 + r4][k8 * 8 + 4 + c4]);
                mma8(s[nj], qf[k8], kf);
            }
        }

        // rpe + mask + exp -> P fragment via shuffle -> O += P V
        const float* rp0 = rpb + (size_t)row0 * WN + c0 + 2 * c4;
        const float* rp1 = rpb + (size_t)row1 * WN + c0 + 2 * c4;
        #pragma unroll
        for (int nj = 0; nj < 8; nj++) {
            int cc = c0 + nj * 8 + 2 * c4;
            float2 ra  = *(const float2*)(rp0 + nj * 8);
            float2 rb2 = *(const float2*)(rp1 + nj * 8);
            int rc0 = regtab[cc], rc1 = regtab[cc + 1];
            float e00 = (rr0 == rc0) ? __expf(s[nj][0] + ra.x)  : 0.f;
            float e01 = (rr0 == rc1) ? __expf(s[nj][1] + ra.y)  : 0.f;
            float e10 = (rr1 == rc0) ? __expf(s[nj][2] + rb2.x) : 0.f;
            float e11 = (rr1 == rc1) ? __expf(s[nj][3] + rb2.y) : 0.f;
            l0 += e00 + e01;
            l1 += e10 + e11;

            float a0 = __shfl_sync(0xffffffffu, e00, src0);
            float b0 = __shfl_sync(0xffffffffu, e01, src0);
            float a1 = __shfl_sync(0xffffffffu, e10, src0);
            float b1 = __shfl_sync(0xffffffffu, e11, src0);
            float a2 = __shfl_sync(0xffffffffu, e00, src1);
            float b2 = __shfl_sync(0xffffffffu, e01, src1);
            float a3 = __shfl_sync(0xffffffffu, e10, src1);
            float b3 = __shfl_sync(0xffffffffu, e11, src1);

            uint32_t pf[4];
            pf[0] = f2tf(oddc ? b0 : a0);
            pf[1] = f2tf(oddc ? b1 : a1);
            pf[2] = f2tf(oddc ? b2 : a2);
            pf[3] = f2tf(oddc ? b3 : a3);

            #pragma unroll
            for (int dj = 0; dj < 4; dj++) {
                uint32_t vf[2];
                vf[0] = f2tf(Vs[cur][nj * 8 +     c4][dj * 8 + r4]);
                vf[1] = f2tf(Vs[cur][nj * 8 + 4 + c4][dj * 8 + r4]);
                mma8(o[dj], pf, vf);
            }
        }
        __syncthreads();
    }

    l0 += __shfl_xor_sync(0xffffffffu, l0, 1);
    l0 += __shfl_xor_sync(0xffffffffu, l0, 2);
    l1 += __shfl_xor_sync(0xffffffffu, l1, 1);
    l1 += __shfl_xor_sync(0xffffffffu, l1, 2);
    float i0 = 1.f / l0, i1 = 1.f / l1;

    float* ob = out + (size_t)(win * WN + qr) * CCH + head * HD;
    #pragma unroll
    for (int nj = 0; nj < 4; nj++) {
        *(float2*)(ob + (size_t)r4       * CCH + nj * 8 + 2 * c4) =
            make_float2(o[nj][0] * i0, o[nj][1] * i0);
        *(float2*)(ob + (size_t)(r4 + 8) * CCH + nj * 8 + 2 * c4) =
            make_float2(o[nj][2] * i1, o[nj][3] * i1);
    }
}

// ---------------------------------------------------------------------------
extern "C" void kernel_launch(void* const* d_in, const int* in_sizes, int n_in,
                              void* d_out, int out_size)
{
    const float* x         = (const float*)d_in[0];
    const int*   rel_index = (const int*)  d_in[2];
    const float* rel_bias  = (const float*)d_in[3];
    const float* qkv_w     = (const float*)d_in[4];
    const float* qkv_b     = (const float*)d_in[5];
    const float* proj_w    = (const float*)d_in[6];
    const float* proj_b    = (const float*)d_in[7];
    const float* n1g       = (const float*)d_in[8];
    const float* n1b       = (const float*)d_in[9];
    const float* n2g       = (const float*)d_in[10];
    const float* n2b       = (const float*)d_in[11];
    const float* w1        = (const float*)d_in[12];
    const float* b1        = (const float*)d_in[13];
    const float* w2        = (const float*)d_in[14];
    const float* b2        = (const float*)d_in[15];
    float* out = (float*)d_out;

    float *xw, *qkv, *rpe, *ao, *y, *h2, *mlp;
    cudaGetSymbolAddress((void**)&xw,  g_xw);
    cudaGetSymbolAddress((void**)&qkv, g_qkv);
    cudaGetSymbolAddress((void**)&rpe, g_rpe);
    cudaGetSymbolAddress((void**)&ao,  g_ao);
    cudaGetSymbolAddress((void**)&y,   g_y);
    cudaGetSymbolAddress((void**)&h2,  g_h2);
    cudaGetSymbolAddress((void**)&mlp, g_mlp);

    ln1_shift_kernel<<<TOK / 8, 256>>>(x, n1g, n1b, xw);
    rpe_kernel<<<(WN * WN) / 256, 256>>>(rel_index, rel_bias, rpe);
    gemm_tf32<0><<<dim3(TOK / 128, 3), 256>>>(xw, qkv_w, qkv_b, qkv, nullptr,
                                              TOK, 384, 128);
    attn_mma<<<dim3(NH, NWIN, 4), 256>>>(qkv, rpe, ao);
    gemm_tf32<3><<<dim3(TOK / 128, 1), 256>>>(ao, proj_w, proj_b, y, x,
                                              TOK, 128, 128);
    ln2_kernel<<<TOK / 8, 256>>>(y, n2g, n2b, h2);
    gemm_tf32<1><<<dim3(TOK / 128, 4), 256>>>(h2, w1, b1, mlp, nullptr,
                                              TOK, 512, 128);
    gemm_tf32<2><<<dim3(TOK / 128, 1), 256>>>(mlp, w2, b2, out, y,
                                              TOK, 128, 512);
}

// round 6
// speedup vs baseline: 4.4154x; 1.1920x over previous
#include <cuda_runtime.h>
#include <math.h>
#include <stdint.h>

// Problem constants: B=1, D=16, H=64, W=64, C=128, WS=8, SS=4, NH=4, hd=32
#define TOK   65536
#define CCH   128
#define NWIN  128
#define WN    512
#define NH    4
#define HD    32
#define MLPH  512

// Scratch
__device__ float g_xw [TOK * CCH];
__device__ float g_qkv[TOK * 384];
__device__ float g_rpe[NH * WN * WN];
__device__ float g_ao [TOK * CCH];
__device__ float g_y  [TOK * CCH];
__device__ float g_h2 [TOK * CCH];
__device__ float g_mlp[TOK * MLPH];
// tf32-grid-rounded weight copies
__device__ float g_wq[384 * 128];
__device__ float g_wp[128 * 128];
__device__ float g_w1[512 * 128];
__device__ float g_w2[128 * 512];

// ---------------------------------------------------------------------------
// Helpers
// ---------------------------------------------------------------------------
__device__ __forceinline__ uint32_t f2tf(float f) {
    uint32_t r;
    asm("cvt.rna.tf32.f32 %0, %1;" : "=r"(r) : "f"(f));
    return r;
}
__device__ __forceinline__ float rtf(float f) {   // round-to-tf32-grid, as fp32
    return __uint_as_float(f2tf(f));
}
__device__ __forceinline__ void mma8(float* c, const uint32_t* a, const uint32_t* b) {
    asm volatile(
        "mma.sync.aligned.m16n8k8.row.col.f32.tf32.tf32.f32 "
        "{%0,%1,%2,%3},{%4,%5,%6,%7},{%8,%9},{%0,%1,%2,%3};"
        : "+f"(c[0]), "+f"(c[1]), "+f"(c[2]), "+f"(c[3])
        : "r"(a[0]), "r"(a[1]), "r"(a[2]), "r"(a[3]), "r"(b[0]), "r"(b[1]));
}
__device__ __forceinline__ void cpa16(float* dst, const float* src) {
    unsigned d = (unsigned)__cvta_generic_to_shared(dst);
    asm volatile("cp.async.cg.shared.global [%0], [%1], 16;" :: "r"(d), "l"(src));
}
#define CP_COMMIT() asm volatile("cp.async.commit_group;")
#define CP_WAIT(n)  asm volatile("cp.async.wait_group %0;" :: "n"(n))

// ---------------------------------------------------------------------------
// Weight rounding: copy 4 weight matrices rounded to the tf32 grid.
// total = 49152 + 16384 + 65536 + 65536 = 196608 -> grid 768 x 256
// ---------------------------------------------------------------------------
__global__ void roundw_kernel(const float* __restrict__ wq, const float* __restrict__ wp,
                              const float* __restrict__ w1, const float* __restrict__ w2,
                              float* __restrict__ oq, float* __restrict__ op,
                              float* __restrict__ o1, float* __restrict__ o2)
{
    int i = blockIdx.x * 256 + threadIdx.x;
    if (i < 49152)       oq[i]          = rtf(wq[i]);
    else if (i < 65536)  op[i - 49152]  = rtf(wp[i - 49152]);
    else if (i < 131072) o1[i - 65536]  = rtf(w1[i - 65536]);
    else                 o2[i - 131072] = rtf(w2[i - 131072]);
}

// ---------------------------------------------------------------------------
// LN1 + roll(-4,-4,-4) + window partition (one warp per token). tf32-rounded out.
// ---------------------------------------------------------------------------
__global__ __launch_bounds__(256) void ln1_shift_kernel(
    const float* __restrict__ x, const float* __restrict__ g,
    const float* __restrict__ b, float* __restrict__ out)
{
    int m    = blockIdx.x * 8 + (threadIdx.x >> 5);
    int lane = threadIdx.x & 31;
    int win = m >> 9, nl = m & 511;
    int wd = win >> 6, wh = (win >> 3) & 7, ww = win & 7;
    int nd = nl >> 6,  nh = (nl >> 3) & 7,  nw = nl & 7;
    int d  = ((wd * 8 + nd) + 4) & 15;
    int hh = ((wh * 8 + nh) + 4) & 63;
    int w  = ((ww * 8 + nw) + 4) & 63;
    int t  = (d * 64 + hh) * 64 + w;

    float4 v = ((const float4*)(x + (size_t)t * CCH))[lane];
    float s  = v.x + v.y + v.z + v.w;
    float s2 = v.x * v.x + v.y * v.y + v.z * v.z + v.w * v.w;
    #pragma unroll
    for (int o = 16; o; o >>= 1) {
        s  += __shfl_xor_sync(0xffffffffu, s,  o);
        s2 += __shfl_xor_sync(0xffffffffu, s2, o);
    }
    float mean = s * (1.f / 128.f);
    float var  = s2 * (1.f / 128.f) - mean * mean;
    float inv  = rsqrtf(var + 1e-5f);
    float4 gg = ((const float4*)g)[lane];
    float4 bb = ((const float4*)b)[lane];
    float4 r;
    r.x = rtf((v.x - mean) * inv * gg.x + bb.x);
    r.y = rtf((v.y - mean) * inv * gg.y + bb.y);
    r.z = rtf((v.z - mean) * inv * gg.z + bb.z);
    r.w = rtf((v.w - mean) * inv * gg.w + bb.w);
    ((float4*)(out + (size_t)m * CCH))[lane] = r;
}

__global__ __launch_bounds__(256) void ln2_kernel(
    const float* __restrict__ x, const float* __restrict__ g,
    const float* __restrict__ b, float* __restrict__ out)
{
    int m    = blockIdx.x * 8 + (threadIdx.x >> 5);
    int lane = threadIdx.x & 31;
    float4 v = ((const float4*)(x + (size_t)m * CCH))[lane];
    float s  = v.x + v.y + v.z + v.w;
    float s2 = v.x * v.x + v.y * v.y + v.z * v.z + v.w * v.w;
    #pragma unroll
    for (int o = 16; o; o >>= 1) {
        s  += __shfl_xor_sync(0xffffffffu, s,  o);
        s2 += __shfl_xor_sync(0xffffffffu, s2, o);
    }
    float mean = s * (1.f / 128.f);
    float var  = s2 * (1.f / 128.f) - mean * mean;
    float inv  = rsqrtf(var + 1e-5f);
    float4 gg = ((const float4*)g)[lane];
    float4 bb = ((const float4*)b)[lane];
    float4 r;
    r.x = rtf((v.x - mean) * inv * gg.x + bb.x);
    r.y = rtf((v.y - mean) * inv * gg.y + bb.y);
    r.z = rtf((v.z - mean) * inv * gg.z + bb.z);
    r.w = rtf((v.w - mean) * inv * gg.w + bb.w);
    ((float4*)(out + (size_t)m * CCH))[lane] = r;
}

// ---------------------------------------------------------------------------
// rpe[h][n][j] = rel_bias[rel_index[n*512+j]*4 + h]
// ---------------------------------------------------------------------------
__global__ void rpe_kernel(const int* __restrict__ ri, const float* __restrict__ rb,
                           float* __restrict__ rpe)
{
    int idx = blockIdx.x * 256 + threadIdx.x;
    int r = ri[idx];
    #pragma unroll
    for (int h = 0; h < NH; h++)
        rpe[h * (WN * WN) + idx] = rb[r * NH + h];
}

// ---------------------------------------------------------------------------
// tf32 GEMM: C[M,N] = A[M,K] @ B[N,K]^T + epilogue.
// Operands pre-rounded to tf32 grid -> raw bit reinterpret, NO inner cvt.
// Block 128x128, BK=16 two-stage cp.async pipeline, 8 warps (2m x 4n).
// MODE 0: +bias, round out   MODE 1: gelu(+bias), round out
// MODE 2: +bias+R[m,n]       MODE 3: +bias+R[t,n] scatter (win-rev + roll+4)
// ---------------------------------------------------------------------------
template <int MODE>
__global__ __launch_bounds__(256) void gemm_tf32(
    const float* __restrict__ A, const float* __restrict__ B,
    const float* __restrict__ bias, float* __restrict__ C,
    const float* __restrict__ R, int M, int N, int K)
{
    __shared__ float As[2][128][20];
    __shared__ float Bs[2][128][20];
    int tid = threadIdx.x, lane = tid & 31, warp = tid >> 5;
    int bm = blockIdx.x * 128, bn = blockIdx.y * 128;
    int wm = (warp >> 2) * 64, wn = (warp & 3) * 32;
    int r4 = lane >> 2, c4 = lane & 3;

    float acc[4][4][4];
    #pragma unroll
    for (int i = 0; i < 4; i++)
        #pragma unroll
        for (int j = 0; j < 4; j++)
            #pragma unroll
            for (int c = 0; c < 4; c++) acc[i][j][c] = 0.f;

    int lr = tid >> 1, lc = (tid & 1) * 8;
    const float* Ag = A + (size_t)(bm + lr) * K + lc;
    const float* Bg = B + (size_t)(bn + lr) * K + lc;

    // stage 0 prologue
    cpa16(&As[0][lr][lc],     Ag);
    cpa16(&As[0][lr][lc + 4], Ag + 4);
    cpa16(&Bs[0][lr][lc],     Bg);
    cpa16(&Bs[0][lr][lc + 4], Bg + 4);
    CP_COMMIT();

    int niter = K >> 4;
    #pragma unroll 1
    for (int it = 0; it < niter; it++) {
        int cur = it & 1;
        if (it + 1 < niter) {
            int nxt = cur ^ 1;
            int kt = (it + 1) * 16;
            cpa16(&As[nxt][lr][lc],     Ag + kt);
            cpa16(&As[nxt][lr][lc + 4], Ag + kt + 4);
            cpa16(&Bs[nxt][lr][lc],     Bg + kt);
            cpa16(&Bs[nxt][lr][lc + 4], Bg + kt + 4);
            CP_COMMIT();
            CP_WAIT(1);
        } else {
            CP_WAIT(0);
        }
        __syncthreads();
        #pragma unroll
        for (int k8 = 0; k8 < 16; k8 += 8) {
            uint32_t af[4][4], bf[4][2];
            #pragma unroll
            for (int i = 0; i < 4; i++) {
                int r = wm + 16 * i;
                af[i][0] = __float_as_uint(As[cur][r +     r4][k8 +     c4]);
                af[i][1] = __float_as_uint(As[cur][r + 8 + r4][k8 +     c4]);
                af[i][2] = __float_as_uint(As[cur][r +     r4][k8 + 4 + c4]);
                af[i][3] = __float_as_uint(As[cur][r + 8 + r4][k8 + 4 + c4]);
            }
            #pragma unroll
            for (int j = 0; j < 4; j++) {
                int c = wn + 8 * j;
                bf[j][0] = __float_as_uint(Bs[cur][c + r4][k8 +     c4]);
                bf[j][1] = __float_as_uint(Bs[cur][c + r4][k8 + 4 + c4]);
            }
            #pragma unroll
            for (int i = 0; i < 4; i++)
                #pragma unroll
                for (int j = 0; j < 4; j++)
                    mma8(acc[i][j], af[i], bf[j]);
        }
        __syncthreads();
    }

    #pragma unroll
    for (int i = 0; i < 4; i++) {
        int r0 = bm + wm + 16 * i + r4;
        #pragma unroll
        for (int h = 0; h < 2; h++) {
            int m = r0 + 8 * h;
            size_t trow = m;
            if (MODE == 3) {
                int win = m >> 9, nl = m & 511;
                int wd = win >> 6, wh = (win >> 3) & 7, ww = win & 7;
                int nd = nl >> 6,  nh = (nl >> 3) & 7,  nw = nl & 7;
                int d  = ((wd * 8 + nd) + 4) & 15;
                int hh = ((wh * 8 + nh) + 4) & 63;
                int w  = ((ww * 8 + nw) + 4) & 63;
                trow = (size_t)((d * 64 + hh) * 64 + w);
            }
            #pragma unroll
            for (int j = 0; j < 4; j++) {
                int c0 = bn + wn + 8 * j + 2 * c4;
                float v0 = acc[i][j][2 * h + 0] + bias[c0];
                float v1 = acc[i][j][2 * h + 1] + bias[c0 + 1];
                if (MODE == 0) {
                    *(float2*)(C + (size_t)m * N + c0) = make_float2(rtf(v0), rtf(v1));
                } else if (MODE == 1) {
                    float g0 = 0.5f * v0 * (1.0f + erff(v0 * 0.70710678118654752f));
                    float g1 = 0.5f * v1 * (1.0f + erff(v1 * 0.70710678118654752f));
                    *(float2*)(C + (size_t)m * N + c0) = make_float2(rtf(g0), rtf(g1));
                } else if (MODE == 2) {
                    float2 rr = *(const float2*)(R + (size_t)m * N + c0);
                    *(float2*)(C + (size_t)m * N + c0) = make_float2(v0 + rr.x, v1 + rr.y);
                } else {
                    float2 rr = *(const float2*)(R + trow * CCH + c0);
                    *(float2*)(C + trow * CCH + c0) = make_float2(v0 + rr.x, v1 + rr.y);
                }
            }
        }
    }
}

// ---------------------------------------------------------------------------
// Tensor-core attention (tf32, operands pre-rounded -> raw bits from smem).
// Block = (head, win, q-tile 128), 8 warps. Double-buffered K/V cp.async.
// P fragment via shuffle transpose. Uniform fast path for unmasked windows.
// ---------------------------------------------------------------------------
__global__ __launch_bounds__(256) void attn_mma(
    const float* __restrict__ qkv, const float* __restrict__ rpe,
    float* __restrict__ out)
{
    __shared__ float Ks[2][64][36];
    __shared__ float Vs[2][64][40];
    __shared__ unsigned char regtab[512];

    int head = blockIdx.x, win = blockIdx.y, qt = blockIdx.z;
    int tid = threadIdx.x, lane = tid & 31, warp = tid >> 5;
    int r4 = lane >> 2, c4 = lane & 3;

    int wd = win >> 6, wh = (win >> 3) & 7, ww = win & 7;
    bool masked_win = (wd == 1) || (wh == 7) || (ww == 7);
    if (masked_win) {
        for (int n = tid; n < 512; n += 256) {
            int nd = n >> 6, nh = (n >> 3) & 7, nw = n & 7;
            int rd = (wd == 1) ? ((nd < 4) ? 1 : 2) : 0;
            int rh = (wh == 7) ? ((nh < 4) ? 1 : 2) : 0;
            int rw = (ww == 7) ? ((nw < 4) ? 1 : 2) : 0;
            regtab[n] = (unsigned char)(rd * 9 + rh * 3 + rw);
        }
    }

    int qr = qt * 128 + warp * 16;
    const float scale = 0.17677669529663687f;
    const float* qb = qkv + (size_t)(win * WN + qr) * 384 + head * HD;
    uint32_t qf[4][4];
    #pragma unroll
    for (int k8 = 0; k8 < 4; k8++) {
        qf[k8][0] = f2tf(scale * qb[(size_t)r4       * 384 + k8 * 8 +     c4]);
        qf[k8][1] = f2tf(scale * qb[(size_t)(r4 + 8) * 384 + k8 * 8 +     c4]);
        qf[k8][2] = f2tf(scale * qb[(size_t)r4       * 384 + k8 * 8 + 4 + c4]);
        qf[k8][3] = f2tf(scale * qb[(size_t)(r4 + 8) * 384 + k8 * 8 + 4 + c4]);
    }

    float o[4][4];
    #pragma unroll
    for (int j = 0; j < 4; j++)
        #pragma unroll
        for (int c = 0; c < 4; c++) o[j][c] = 0.f;
    float l0 = 0.f, l1 = 0.f;

    __syncthreads();
    int row0 = qr + r4, row1 = row0 + 8;
    int rr0 = 0, rr1 = 0;
    if (masked_win) { rr0 = regtab[row0]; rr1 = regtab[row1]; }
    const float* rpb = rpe + ((size_t)head << 18);

    int ldrow = tid >> 2, ldsg = (tid & 3) * 8;
    int src0 = (lane & ~3) | (c4 >> 1);
    int src1 = src0 + 2;
    bool oddc = (c4 & 1);

    {
        const float* kb = qkv + (size_t)(win * WN + ldrow) * 384 + 128 + head * HD + ldsg;
        cpa16(&Ks[0][ldrow][ldsg],     kb);
        cpa16(&Ks[0][ldrow][ldsg + 4], kb + 4);
        cpa16(&Vs[0][ldrow][ldsg],     kb + 128);
        cpa16(&Vs[0][ldrow][ldsg + 4], kb + 132);
        CP_COMMIT();
    }

    #pragma unroll 1
    for (int ci = 0; ci < 8; ci++) {
        int cur = ci & 1;
        if (ci + 1 < 8) {
            int nxt = cur ^ 1;
            const float* kb = qkv + (size_t)(win * WN + (ci + 1) * 64 + ldrow) * 384
                              + 128 + head * HD + ldsg;
            cpa16(&Ks[nxt][ldrow][ldsg],     kb);
            cpa16(&Ks[nxt][ldrow][ldsg + 4], kb + 4);
            cpa16(&Vs[nxt][ldrow][ldsg],     kb + 128);
            cpa16(&Vs[nxt][ldrow][ldsg + 4], kb + 132);
            CP_COMMIT();
            CP_WAIT(1);
        } else {
            CP_WAIT(0);
        }
        __syncthreads();
        int c0 = ci * 64;

        // S = Q K^T  (16 x 64 per warp)
        float s[8][4];
        #pragma unroll
        for (int nj = 0; nj < 8; nj++) {
            s[nj][0] = s[nj][1] = s[nj][2] = s[nj][3] = 0.f;
            #pragma unroll
            for (int k8 = 0; k8 < 4; k8++) {
                uint32_t kf[2];
                kf[0] = __float_as_uint(Ks[cur][nj * 8 + r4][k8 * 8 +     c4]);
                kf[1] = __float_as_uint(Ks[cur][nj * 8 + r4][k8 * 8 + 4 + c4]);
                mma8(s[nj], qf[k8], kf);
            }
        }

        // rpe (+mask) + exp -> P fragment via shuffle -> O += P V
        const float* rp0 = rpb + (size_t)row0 * WN + c0 + 2 * c4;
        const float* rp1 = rpb + (size_t)row1 * WN + c0 + 2 * c4;
        #pragma unroll
        for (int nj = 0; nj < 8; nj++) {
            float2 ra  = *(const float2*)(rp0 + nj * 8);
            float2 rb2 = *(const float2*)(rp1 + nj * 8);
            float e00, e01, e10, e11;
            if (masked_win) {
                int cc = c0 + nj * 8 + 2 * c4;
                int rc0 = regtab[cc], rc1 = regtab[cc + 1];
                e00 = (rr0 == rc0) ? __expf(s[nj][0] + ra.x)  : 0.f;
                e01 = (rr0 == rc1) ? __expf(s[nj][1] + ra.y)  : 0.f;
                e10 = (rr1 == rc0) ? __expf(s[nj][2] + rb2.x) : 0.f;
                e11 = (rr1 == rc1) ? __expf(s[nj][3] + rb2.y) : 0.f;
            } else {
                e00 = __expf(s[nj][0] + ra.x);
                e01 = __expf(s[nj][1] + ra.y);
                e10 = __expf(s[nj][2] + rb2.x);
                e11 = __expf(s[nj][3] + rb2.y);
            }
            l0 += e00 + e01;
            l1 += e10 + e11;

            float a0 = __shfl_sync(0xffffffffu, e00, src0);
            float b0 = __shfl_sync(0xffffffffu, e01, src0);
            float a1 = __shfl_sync(0xffffffffu, e10, src0);
            float b1 = __shfl_sync(0xffffffffu, e11, src0);
            float a2 = __shfl_sync(0xffffffffu, e00, src1);
            float b2 = __shfl_sync(0xffffffffu, e01, src1);
            float a3 = __shfl_sync(0xffffffffu, e10, src1);
            float b3 = __shfl_sync(0xffffffffu, e11, src1);

            uint32_t pf[4];
            pf[0] = f2tf(oddc ? b0 : a0);
            pf[1] = f2tf(oddc ? b1 : a1);
            pf[2] = f2tf(oddc ? b2 : a2);
            pf[3] = f2tf(oddc ? b3 : a3);

            #pragma unroll
            for (int dj = 0; dj < 4; dj++) {
                uint32_t vf[2];
                vf[0] = __float_as_uint(Vs[cur][nj * 8 +     c4][dj * 8 + r4]);
                vf[1] = __float_as_uint(Vs[cur][nj * 8 + 4 + c4][dj * 8 + r4]);
                mma8(o[dj], pf, vf);
            }
        }
        __syncthreads();
    }

    l0 += __shfl_xor_sync(0xffffffffu, l0, 1);
    l0 += __shfl_xor_sync(0xffffffffu, l0, 2);
    l1 += __shfl_xor_sync(0xffffffffu, l1, 1);
    l1 += __shfl_xor_sync(0xffffffffu, l1, 2);
    float i0 = 1.f / l0, i1 = 1.f / l1;

    // store attn output rounded to tf32 grid (operand of proj GEMM)
    float* ob = out + (size_t)(win * WN + qr) * CCH + head * HD;
    #pragma unroll
    for (int nj = 0; nj < 4; nj++) {
        *(float2*)(ob + (size_t)r4       * CCH + nj * 8 + 2 * c4) =
            make_float2(rtf(o[nj][0] * i0), rtf(o[nj][1] * i0));
        *(float2*)(ob + (size_t)(r4 + 8) * CCH + nj * 8 + 2 * c4) =
            make_float2(rtf(o[nj][2] * i1), rtf(o[nj][3] * i1));
    }
}

// ---------------------------------------------------------------------------
extern "C" void kernel_launch(void* const* d_in, const int* in_sizes, int n_in,
                              void* d_out, int out_size)
{
    const float* x         = (const float*)d_in[0];
    const int*   rel_index = (const int*)  d_in[2];
    const float* rel_bias  = (const float*)d_in[3];
    const float* qkv_w     = (const float*)d_in[4];
    const float* qkv_b     = (const float*)d_in[5];
    const float* proj_w    = (const float*)d_in[6];
    const float* proj_b    = (const float*)d_in[7];
    const float* n1g       = (const float*)d_in[8];
    const float* n1b       = (const float*)d_in[9];
    const float* n2g       = (const float*)d_in[10];
    const float* n2b       = (const float*)d_in[11];
    const float* w1        = (const float*)d_in[12];
    const float* b1        = (const float*)d_in[13];
    const float* w2        = (const float*)d_in[14];
    const float* b2        = (const float*)d_in[15];
    float* out = (float*)d_out;

    float *xw, *qkv, *rpe, *ao, *y, *h2, *mlp, *wq, *wp, *ww1, *ww2;
    cudaGetSymbolAddress((void**)&xw,  g_xw);
    cudaGetSymbolAddress((void**)&qkv, g_qkv);
    cudaGetSymbolAddress((void**)&rpe, g_rpe);
    cudaGetSymbolAddress((void**)&ao,  g_ao);
    cudaGetSymbolAddress((void**)&y,   g_y);
    cudaGetSymbolAddress((void**)&h2,  g_h2);
    cudaGetSymbolAddress((void**)&mlp, g_mlp);
    cudaGetSymbolAddress((void**)&wq,  g_wq);
    cudaGetSymbolAddress((void**)&wp,  g_wp);
    cudaGetSymbolAddress((void**)&ww1, g_w1);
    cudaGetSymbolAddress((void**)&ww2, g_w2);

    roundw_kernel<<<768, 256>>>(qkv_w, proj_w, w1, w2, wq, wp, ww1, ww2);
    ln1_shift_kernel<<<TOK / 8, 256>>>(x, n1g, n1b, xw);
    rpe_kernel<<<(WN * WN) / 256, 256>>>(rel_index, rel_bias, rpe);
    gemm_tf32<0><<<dim3(TOK / 128, 3), 256>>>(xw, wq, qkv_b, qkv, nullptr,
                                              TOK, 384, 128);
    attn_mma<<<dim3(NH, NWIN, 4), 256>>>(qkv, rpe, ao);
    gemm_tf32<3><<<dim3(TOK / 128, 1), 256>>>(ao, wp, proj_b, y, x,
                                              TOK, 128, 128);
    ln2_kernel<<<TOK / 8, 256>>>(y, n2g, n2b, h2);
    gemm_tf32<1><<<dim3(TOK / 128, 4), 256>>>(h2, ww1, b1, mlp, nullptr,
                                              TOK, 512, 128);
    gemm_tf32<2><<<dim3(TOK / 128, 1), 256>>>(mlp, ww2, b2, out, y,
                                              TOK, 128, 512);
}

// round 7
// speedup vs baseline: 6.7207x; 1.5221x over previous
#include <cuda_runtime.h>
#include <cuda_bf16.h>
#include <math.h>
#include <stdint.h>

// Problem constants: B=1, D=16, H=64, W=64, C=128, WS=8, SS=4, NH=4, hd=32
#define TOK   65536
#define CCH   128
#define NWIN  128
#define WN    512
#define NH    4
#define HD    32
#define MLPH  512

typedef __nv_bfloat16 bf16;

// Scratch
__device__ bf16  g_xw [TOK * CCH];      // LN1+shift, bf16
__device__ bf16  g_qkv[TOK * 384];      // qkv (q pre-scaled), bf16
__device__ float g_rpe[NH * WN * WN];
__device__ bf16  g_ao [TOK * CCH];      // attention out, bf16
__device__ float g_y  [TOK * CCH];      // x + proj (f32, residual trunk)
__device__ bf16  g_h2 [TOK * CCH];      // LN2 out, bf16
__device__ bf16  g_mlp[TOK * MLPH];     // gelu(mlp1), bf16
// bf16 weights
__device__ bf16  g_wq[384 * 128];
__device__ bf16  g_wp[128 * 128];
__device__ bf16  g_w1[512 * 128];
__device__ bf16  g_w2[128 * 512];
__device__ float g_qb[384];             // qkv bias, q part pre-scaled

// ---------------------------------------------------------------------------
// Helpers
// ---------------------------------------------------------------------------
__device__ __forceinline__ uint32_t packbf(float lo, float hi) {
    uint32_t r;
    asm("cvt.rn.bf16x2.f32 %0, %1, %2;" : "=r"(r) : "f"(hi), "f"(lo));
    return r;
}
__device__ __forceinline__ void mmabf(float* c, const uint32_t* a, const uint32_t* b) {
    asm volatile(
        "mma.sync.aligned.m16n8k16.row.col.f32.bf16.bf16.f32 "
        "{%0,%1,%2,%3},{%4,%5,%6,%7},{%8,%9},{%0,%1,%2,%3};"
        : "+f"(c[0]), "+f"(c[1]), "+f"(c[2]), "+f"(c[3])
        : "r"(a[0]), "r"(a[1]), "r"(a[2]), "r"(a[3]), "r"(b[0]), "r"(b[1]));
}
__device__ __forceinline__ void ldmx4t(uint32_t* r, const void* p) {
    unsigned a = (unsigned)__cvta_generic_to_shared(p);
    asm volatile("ldmatrix.sync.aligned.m8n8.x4.trans.shared.b16 {%0,%1,%2,%3}, [%4];"
        : "=r"(r[0]), "=r"(r[1]), "=r"(r[2]), "=r"(r[3]) : "r"(a));
}
__device__ __forceinline__ void cpa16(void* dst, const void* src) {
    unsigned d = (unsigned)__cvta_generic_to_shared(dst);
    asm volatile("cp.async.cg.shared.global [%0], [%1], 16;" :: "r"(d), "l"(src));
}
#define CP_COMMIT() asm volatile("cp.async.commit_group;")
#define CP_WAIT(n)  asm volatile("cp.async.wait_group %0;" :: "n"(n))

// ---------------------------------------------------------------------------
// Weight conversion to bf16 (+ fold attention scale into q weights/bias)
// ---------------------------------------------------------------------------
__global__ void roundw_kernel(const float* __restrict__ wq, const float* __restrict__ wp,
                              const float* __restrict__ w1, const float* __restrict__ w2,
                              const float* __restrict__ qb,
                              bf16* __restrict__ oq, bf16* __restrict__ op,
                              bf16* __restrict__ o1, bf16* __restrict__ o2,
                              float* __restrict__ oqb)
{
    const float scale = 0.17677669529663687f;   // 1/sqrt(32)
    int i = blockIdx.x * 256 + threadIdx.x;
    if (i < 384) oqb[i] = qb[i] * ((i < 128) ? scale : 1.f);
    if (i < 49152) {
        float v = wq[i] * (((i >> 7) < 128) ? scale : 1.f);
        oq[i] = __float2bfloat16(v);
    } else if (i < 65536)  op[i - 49152]  = __float2bfloat16(wp[i - 49152]);
    else if (i < 131072)   o1[i - 65536]  = __float2bfloat16(w1[i - 65536]);
    else                   o2[i - 131072] = __float2bfloat16(w2[i - 131072]);
}

// ---------------------------------------------------------------------------
// LN1 + roll(-4,-4,-4) + window partition; bf16 out. One warp per token.
// ---------------------------------------------------------------------------
__global__ __launch_bounds__(256) void ln1_shift_kernel(
    const float* __restrict__ x, const float* __restrict__ g,
    const float* __restrict__ b, bf16* __restrict__ out)
{
    int m    = blockIdx.x * 8 + (threadIdx.x >> 5);
    int lane = threadIdx.x & 31;
    int win = m >> 9, nl = m & 511;
    int wd = win >> 6, wh = (win >> 3) & 7, ww = win & 7;
    int nd = nl >> 6,  nh = (nl >> 3) & 7,  nw = nl & 7;
    int d  = ((wd * 8 + nd) + 4) & 15;
    int hh = ((wh * 8 + nh) + 4) & 63;
    int w  = ((ww * 8 + nw) + 4) & 63;
    int t  = (d * 64 + hh) * 64 + w;

    float4 v = ((const float4*)(x + (size_t)t * CCH))[lane];
    float s  = v.x + v.y + v.z + v.w;
    float s2 = v.x * v.x + v.y * v.y + v.z * v.z + v.w * v.w;
    #pragma unroll
    for (int o = 16; o; o >>= 1) {
        s  += __shfl_xor_sync(0xffffffffu, s,  o);
        s2 += __shfl_xor_sync(0xffffffffu, s2, o);
    }
    float mean = s * (1.f / 128.f);
    float var  = s2 * (1.f / 128.f) - mean * mean;
    float inv  = rsqrtf(var + 1e-5f);
    float4 gg = ((const float4*)g)[lane];
    float4 bb = ((const float4*)b)[lane];
    uint32_t p0 = packbf((v.x - mean) * inv * gg.x + bb.x,
                         (v.y - mean) * inv * gg.y + bb.y);
    uint32_t p1 = packbf((v.z - mean) * inv * gg.z + bb.z,
                         (v.w - mean) * inv * gg.w + bb.w);
    *(uint2*)(out + (size_t)m * CCH + lane * 4) = make_uint2(p0, p1);
}

__global__ __launch_bounds__(256) void ln2_kernel(
    const float* __restrict__ x, const float* __restrict__ g,
    const float* __restrict__ b, bf16* __restrict__ out)
{
    int m    = blockIdx.x * 8 + (threadIdx.x >> 5);
    int lane = threadIdx.x & 31;
    float4 v = ((const float4*)(x + (size_t)m * CCH))[lane];
    float s  = v.x + v.y + v.z + v.w;
    float s2 = v.x * v.x + v.y * v.y + v.z * v.z + v.w * v.w;
    #pragma unroll
    for (int o = 16; o; o >>= 1) {
        s  += __shfl_xor_sync(0xffffffffu, s,  o);
        s2 += __shfl_xor_sync(0xffffffffu, s2, o);
    }
    float mean = s * (1.f / 128.f);
    float var  = s2 * (1.f / 128.f) - mean * mean;
    float inv  = rsqrtf(var + 1e-5f);
    float4 gg = ((const float4*)g)[lane];
    float4 bb = ((const float4*)b)[lane];
    uint32_t p0 = packbf((v.x - mean) * inv * gg.x + bb.x,
                         (v.y - mean) * inv * gg.y + bb.y);
    uint32_t p1 = packbf((v.z - mean) * inv * gg.z + bb.z,
                         (v.w - mean) * inv * gg.w + bb.w);
    *(uint2*)(out + (size_t)m * CCH + lane * 4) = make_uint2(p0, p1);
}

// ---------------------------------------------------------------------------
// rpe[h][n][j] = rel_bias[rel_index[n*512+j]*4 + h]
// ---------------------------------------------------------------------------
__global__ void rpe_kernel(const int* __restrict__ ri, const float* __restrict__ rb,
                           float* __restrict__ rpe)
{
    int idx = blockIdx.x * 256 + threadIdx.x;
    int r = ri[idx];
    #pragma unroll
    for (int h = 0; h < NH; h++)
        rpe[h * (WN * WN) + idx] = rb[r * NH + h];
}

// ---------------------------------------------------------------------------
// bf16 GEMM: C[M,N] = A[M,K] @ B[N,K]^T + epilogue (fp32 accumulate).
// Block 128x128, BK=32 two-stage cp.async pipeline, 8 warps (2m x 4n).
// MODE 0: +bias -> bf16        MODE 1: gelu(+bias) -> bf16
// MODE 2: +bias+R[m,n] -> f32  MODE 3: +bias+R[t,n] scatter -> f32
// ---------------------------------------------------------------------------
template <int MODE>
__global__ __launch_bounds__(256) void gemm_bf16(
    const bf16* __restrict__ A, const bf16* __restrict__ B,
    const float* __restrict__ bias, void* __restrict__ Cv,
    const float* __restrict__ R, int M, int N, int K)
{
    __shared__ bf16 As[2][128][40];
    __shared__ bf16 Bs[2][128][40];
    int tid = threadIdx.x, lane = tid & 31, warp = tid >> 5;
    int bm = blockIdx.x * 128, bn = blockIdx.y * 128;
    int wm = (warp >> 2) * 64, wn = (warp & 3) * 32;
    int r4 = lane >> 2, c4 = lane & 3;

    float acc[4][4][4];
    #pragma unroll
    for (int i = 0; i < 4; i++)
        #pragma unroll
        for (int j = 0; j < 4; j++)
            #pragma unroll
            for (int c = 0; c < 4; c++) acc[i][j][c] = 0.f;

    int lr = tid >> 1, lc = (tid & 1) * 16;
    const bf16* Ag = A + (size_t)(bm + lr) * K + lc;
    const bf16* Bg = B + (size_t)(bn + lr) * K + lc;

    cpa16(&As[0][lr][lc],     Ag);
    cpa16(&As[0][lr][lc + 8], Ag + 8);
    cpa16(&Bs[0][lr][lc],     Bg);
    cpa16(&Bs[0][lr][lc + 8], Bg + 8);
    CP_COMMIT();

    int niter = K >> 5;
    #pragma unroll 1
    for (int it = 0; it < niter; it++) {
        int cur = it & 1;
        if (it + 1 < niter) {
            int nxt = cur ^ 1;
            int kt = (it + 1) * 32;
            cpa16(&As[nxt][lr][lc],     Ag + kt);
            cpa16(&As[nxt][lr][lc + 8], Ag + kt + 8);
            cpa16(&Bs[nxt][lr][lc],     Bg + kt);
            cpa16(&Bs[nxt][lr][lc + 8], Bg + kt + 8);
            CP_COMMIT();
            CP_WAIT(1);
        } else {
            CP_WAIT(0);
        }
        __syncthreads();
        #pragma unroll
        for (int k16 = 0; k16 < 32; k16 += 16) {
            uint32_t af[4][4], bf[4][2];
            #pragma unroll
            for (int i = 0; i < 4; i++) {
                int r = wm + 16 * i;
                af[i][0] = *(const uint32_t*)&As[cur][r +     r4][k16 + 2 * c4];
                af[i][1] = *(const uint32_t*)&As[cur][r + 8 + r4][k16 + 2 * c4];
                af[i][2] = *(const uint32_t*)&As[cur][r +     r4][k16 + 2 * c4 + 8];
                af[i][3] = *(const uint32_t*)&As[cur][r + 8 + r4][k16 + 2 * c4 + 8];
            }
            #pragma unroll
            for (int j = 0; j < 4; j++) {
                int c = wn + 8 * j;
                bf[j][0] = *(const uint32_t*)&Bs[cur][c + r4][k16 + 2 * c4];
                bf[j][1] = *(const uint32_t*)&Bs[cur][c + r4][k16 + 2 * c4 + 8];
            }
            #pragma unroll
            for (int i = 0; i < 4; i++)
                #pragma unroll
                for (int j = 0; j < 4; j++)
                    mmabf(acc[i][j], af[i], bf[j]);
        }
        __syncthreads();
    }

    #pragma unroll
    for (int i = 0; i < 4; i++) {
        int r0 = bm + wm + 16 * i + r4;
        #pragma unroll
        for (int h = 0; h < 2; h++) {
            int m = r0 + 8 * h;
            size_t trow = m;
            if (MODE == 3) {
                int win = m >> 9, nl = m & 511;
                int wd = win >> 6, wh = (win >> 3) & 7, ww = win & 7;
                int nd = nl >> 6,  nh = (nl >> 3) & 7,  nw = nl & 7;
                int d  = ((wd * 8 + nd) + 4) & 15;
                int hh = ((wh * 8 + nh) + 4) & 63;
                int w  = ((ww * 8 + nw) + 4) & 63;
                trow = (size_t)((d * 64 + hh) * 64 + w);
            }
            #pragma unroll
            for (int j = 0; j < 4; j++) {
                int c0 = bn + wn + 8 * j + 2 * c4;
                float v0 = acc[i][j][2 * h + 0] + bias[c0];
                float v1 = acc[i][j][2 * h + 1] + bias[c0 + 1];
                if (MODE == 0) {
                    *(uint32_t*)((bf16*)Cv + (size_t)m * N + c0) = packbf(v0, v1);
                } else if (MODE == 1) {
                    float g0 = 0.5f * v0 * (1.0f + erff(v0 * 0.70710678118654752f));
                    float g1 = 0.5f * v1 * (1.0f + erff(v1 * 0.70710678118654752f));
                    *(uint32_t*)((bf16*)Cv + (size_t)m * N + c0) = packbf(g0, g1);
                } else if (MODE == 2) {
                    float2 rr = *(const float2*)(R + (size_t)m * N + c0);
                    *(float2*)((float*)Cv + (size_t)m * N + c0) =
                        make_float2(v0 + rr.x, v1 + rr.y);
                } else {
                    float2 rr = *(const float2*)(R + trow * CCH + c0);
                    *(float2*)((float*)Cv + trow * CCH + c0) =
                        make_float2(v0 + rr.x, v1 + rr.y);
                }
            }
        }
    }
}

// ---------------------------------------------------------------------------
// bf16 tensor-core attention. Block = (head, win, q-tile 128), 8 warps.
// S accumulator fragment maps DIRECTLY to P A-fragment (no shuffles).
// V B-fragments via ldmatrix.x4.trans. Double-buffered K/V cp.async.
// ---------------------------------------------------------------------------
__global__ __launch_bounds__(256) void attn_mma(
    const bf16* __restrict__ qkv, const float* __restrict__ rpe,
    bf16* __restrict__ out)
{
    __shared__ bf16 Ks[2][64][40];
    __shared__ bf16 Vs[2][64][40];
    __shared__ unsigned char regtab[512];

    int head = blockIdx.x, win = blockIdx.y, qt = blockIdx.z;
    int tid = threadIdx.x, lane = tid & 31, warp = tid >> 5;
    int r4 = lane >> 2, c4 = lane & 3;

    int wd = win >> 6, wh = (win >> 3) & 7, ww = win & 7;
    bool masked_win = (wd == 1) || (wh == 7) || (ww == 7);
    if (masked_win) {
        for (int n = tid; n < 512; n += 256) {
            int nd = n >> 6, nh = (n >> 3) & 7, nw = n & 7;
            int rd = (wd == 1) ? ((nd < 4) ? 1 : 2) : 0;
            int rh = (wh == 7) ? ((nh < 4) ? 1 : 2) : 0;
            int rw = (ww == 7) ? ((nw < 4) ? 1 : 2) : 0;
            regtab[n] = (unsigned char)(rd * 9 + rh * 3 + rw);
        }
    }

    int qr = qt * 128 + warp * 16;
    const bf16* qb = qkv + (size_t)(win * WN + qr) * 384 + head * HD;
    uint32_t qf[2][4];   // q already scaled at QKV-GEMM time
    #pragma unroll
    for (int kb = 0; kb < 2; kb++) {
        qf[kb][0] = *(const uint32_t*)(qb + (size_t)r4       * 384 + kb * 16 + 2 * c4);
        qf[kb][1] = *(const uint32_t*)(qb + (size_t)(r4 + 8) * 384 + kb * 16 + 2 * c4);
        qf[kb][2] = *(const uint32_t*)(qb + (size_t)r4       * 384 + kb * 16 + 2 * c4 + 8);
        qf[kb][3] = *(const uint32_t*)(qb + (size_t)(r4 + 8) * 384 + kb * 16 + 2 * c4 + 8);
    }

    float o[4][4];
    #pragma unroll
    for (int j = 0; j < 4; j++)
        #pragma unroll
        for (int c = 0; c < 4; c++) o[j][c] = 0.f;
    float l0 = 0.f, l1 = 0.f;

    __syncthreads();
    int row0 = qr + r4, row1 = row0 + 8;
    int rr0 = 0, rr1 = 0;
    if (masked_win) { rr0 = regtab[row0]; rr1 = regtab[row1]; }
    const float* rpb = rpe + ((size_t)head << 18);

    int ldrow = tid >> 2, ldsg = (tid & 3) * 8;
    // ldmatrix.x4.trans addressing for V
    int vrow = (lane & 7) + ((lane >> 3) & 1) * 8;
    int vcol8 = ((lane >> 4) & 1) * 8;

    {
        const bf16* kbp = qkv + (size_t)(win * WN + ldrow) * 384 + 128 + head * HD + ldsg;
        cpa16(&Ks[0][ldrow][ldsg], kbp);
        cpa16(&Vs[0][ldrow][ldsg], kbp + 128);
        CP_COMMIT();
    }

    #pragma unroll 1
    for (int ci = 0; ci < 8; ci++) {
        int cur = ci & 1;
        if (ci + 1 < 8) {
            int nxt = cur ^ 1;
            const bf16* kbp = qkv + (size_t)(win * WN + (ci + 1) * 64 + ldrow) * 384
                              + 128 + head * HD + ldsg;
            cpa16(&Ks[nxt][ldrow][ldsg], kbp);
            cpa16(&Vs[nxt][ldrow][ldsg], kbp + 128);
            CP_COMMIT();
            CP_WAIT(1);
        } else {
            CP_WAIT(0);
        }
        __syncthreads();
        int c0 = ci * 64;

        // S = Q K^T  (16 x 64 per warp): 8 n-blocks x 2 k16
        float s[8][4];
        #pragma unroll
        for (int nj = 0; nj < 8; nj++) {
            s[nj][0] = s[nj][1] = s[nj][2] = s[nj][3] = 0.f;
            #pragma unroll
            for (int kb = 0; kb < 2; kb++) {
                uint32_t kf[2];
                kf[0] = *(const uint32_t*)&Ks[cur][nj * 8 + r4][kb * 16 + 2 * c4];
                kf[1] = *(const uint32_t*)&Ks[cur][nj * 8 + r4][kb * 16 + 2 * c4 + 8];
                mmabf(s[nj], qf[kb], kf);
            }
        }

        // per k16 key block: exp -> P frag (direct pack) -> O += P V
        #pragma unroll
        for (int kb = 0; kb < 4; kb++) {
            float e[2][4];
            #pragma unroll
            for (int half = 0; half < 2; half++) {
                int nj = 2 * kb + half;
                const float* rp0 = rpb + (size_t)row0 * WN + c0 + nj * 8 + 2 * c4;
                const float* rp1 = rpb + (size_t)row1 * WN + c0 + nj * 8 + 2 * c4;
                float2 ra  = *(const float2*)rp0;
                float2 rb2 = *(const float2*)rp1;
                float e00, e01, e10, e11;
                if (masked_win) {
                    int cc = c0 + nj * 8 + 2 * c4;
                    int rc0 = regtab[cc], rc1 = regtab[cc + 1];
                    e00 = (rr0 == rc0) ? __expf(s[nj][0] + ra.x)  : 0.f;
                    e01 = (rr0 == rc1) ? __expf(s[nj][1] + ra.y)  : 0.f;
                    e10 = (rr1 == rc0) ? __expf(s[nj][2] + rb2.x) : 0.f;
                    e11 = (rr1 == rc1) ? __expf(s[nj][3] + rb2.y) : 0.f;
                } else {
                    e00 = __expf(s[nj][0] + ra.x);
                    e01 = __expf(s[nj][1] + ra.y);
                    e10 = __expf(s[nj][2] + rb2.x);
                    e11 = __expf(s[nj][3] + rb2.y);
                }
                l0 += e00 + e01;
                l1 += e10 + e11;
                e[half][0] = e00; e[half][1] = e01;
                e[half][2] = e10; e[half][3] = e11;
            }
            uint32_t pa[4];
            pa[0] = packbf(e[0][0], e[0][1]);
            pa[1] = packbf(e[0][2], e[0][3]);
            pa[2] = packbf(e[1][0], e[1][1]);
            pa[3] = packbf(e[1][2], e[1][3]);

            // V fragments: two ldmatrix.x4.trans cover d-cols 0..15 and 16..31
            uint32_t vb[8];
            ldmx4t(vb,     &Vs[cur][kb * 16 + vrow][vcol8]);
            ldmx4t(vb + 4, &Vs[cur][kb * 16 + vrow][16 + vcol8]);
            mmabf(o[0], pa, vb);
            mmabf(o[1], pa, vb + 2);
            mmabf(o[2], pa, vb + 4);
            mmabf(o[3], pa, vb + 6);
        }
        __syncthreads();
    }

    l0 += __shfl_xor_sync(0xffffffffu, l0, 1);
    l0 += __shfl_xor_sync(0xffffffffu, l0, 2);
    l1 += __shfl_xor_sync(0xffffffffu, l1, 1);
    l1 += __shfl_xor_sync(0xffffffffu, l1, 2);
    float i0 = 1.f / l0, i1 = 1.f / l1;

    bf16* ob = out + (size_t)(win * WN + qr) * CCH + head * HD;
    #pragma unroll
    for (int dj = 0; dj < 4; dj++) {
        *(uint32_t*)(ob + (size_t)r4       * CCH + dj * 8 + 2 * c4) =
            packbf(o[dj][0] * i0, o[dj][1] * i0);
        *(uint32_t*)(ob + (size_t)(r4 + 8) * CCH + dj * 8 + 2 * c4) =
            packbf(o[dj][2] * i1, o[dj][3] * i1);
    }
}

// ---------------------------------------------------------------------------
extern "C" void kernel_launch(void* const* d_in, const int* in_sizes, int n_in,
                              void* d_out, int out_size)
{
    const float* x         = (const float*)d_in[0];
    const int*   rel_index = (const int*)  d_in[2];
    const float* rel_bias  = (const float*)d_in[3];
    const float* qkv_w     = (const float*)d_in[4];
    const float* qkv_b     = (const float*)d_in[5];
    const float* proj_w    = (const float*)d_in[6];
    const float* proj_b    = (const float*)d_in[7];
    const float* n1g       = (const float*)d_in[8];
    const float* n1b       = (const float*)d_in[9];
    const float* n2g       = (const float*)d_in[10];
    const float* n2b       = (const float*)d_in[11];
    const float* w1        = (const float*)d_in[12];
    const float* b1        = (const float*)d_in[13];
    const float* w2        = (const float*)d_in[14];
    const float* b2        = (const float*)d_in[15];
    float* out = (float*)d_out;

    bf16 *xw, *qkv, *ao, *h2, *mlp, *wq, *wp, *ww1, *ww2;
    float *rpe, *y, *qb;
    cudaGetSymbolAddress((void**)&xw,  g_xw);
    cudaGetSymbolAddress((void**)&qkv, g_qkv);
    cudaGetSymbolAddress((void**)&rpe, g_rpe);
    cudaGetSymbolAddress((void**)&ao,  g_ao);
    cudaGetSymbolAddress((void**)&y,   g_y);
    cudaGetSymbolAddress((void**)&h2,  g_h2);
    cudaGetSymbolAddress((void**)&mlp, g_mlp);
    cudaGetSymbolAddress((void**)&wq,  g_wq);
    cudaGetSymbolAddress((void**)&wp,  g_wp);
    cudaGetSymbolAddress((void**)&ww1, g_w1);
    cudaGetSymbolAddress((void**)&ww2, g_w2);
    cudaGetSymbolAddress((void**)&qb,  g_qb);

    roundw_kernel<<<768, 256>>>(qkv_w, proj_w, w1, w2, qkv_b, wq, wp, ww1, ww2, qb);
    ln1_shift_kernel<<<TOK / 8, 256>>>(x, n1g, n1b, xw);
    rpe_kernel<<<(WN * WN) / 256, 256>>>(rel_index, rel_bias, rpe);
    gemm_bf16<0><<<dim3(TOK / 128, 3), 256>>>(xw, wq, qb, qkv, nullptr,
                                              TOK, 384, 128);
    attn_mma<<<dim3(NH, NWIN, 4), 256>>>(qkv, rpe, ao);
    gemm_bf16<3><<<dim3(TOK / 128, 1), 256>>>(ao, wp, proj_b, y, x,
                                              TOK, 128, 128);
    ln2_kernel<<<TOK / 8, 256>>>(y, n2g, n2b, h2);
    gemm_bf16<1><<<dim3(TOK / 128, 4), 256>>>(h2, ww1, b1, mlp, nullptr,
                                              TOK, 512, 128);
    gemm_bf16<2><<<dim3(TOK / 128, 1), 256>>>(mlp, ww2, b2, out, y,
                                              TOK, 128, 512);
}